// round 3
// baseline (speedup 1.0000x reference)
#include <cuda_runtime.h>
#include <math.h>

#define EPS      1e-5f
#define LSEQ     32
#define DM       128
#define CIN      96
#define COUT     12
#define DIN      256
#define DST      16
#define NH       8
#define CDIM     288          // DIN + 2*DST
#define EPROJ    552          // 2*DIN + 2*DST + NH
#define HS_STRIDE 132         // 128 + 4 pad (bank-conflict-free lane=t stores, float4 aligned)
#define NT       256

// shared memory layout (floats)
#define OFF_BUF   0                         // CIN*LSEQ      = 3072
#define OFF_HS    (OFF_BUF + CIN*LSEQ)      // LSEQ*132      = 4224
#define OFF_ZX    (OFF_HS + LSEQ*HS_STRIDE) // LSEQ*552      = 17664
#define OFF_BNW   (OFF_ZX + LSEQ*EPROJ)     // 128
#define OFF_DT    (OFF_BNW + DM)            // 256
#define OFF_DA    (OFF_DT + LSEQ*NH)        // 256
#define OFF_INV   (OFF_DA + LSEQ*NH)        // 32
#define OFF_INV2  (OFF_INV + LSEQ)          // 32
#define OFF_ACC   (OFF_INV2 + LSEQ)         // 128
#define SMEM_FLOATS (OFF_ACC + DM)          // 25792 floats = 103168 B

__device__ __forceinline__ float sigmoidf_(float v) {
    return 1.f / (1.f + __expf(-v));
}

__global__ void __launch_bounds__(NT, 2) mamba_actor_kernel(
    const float* __restrict__ x,        // (B, 96)
    const float* __restrict__ buffer,   // (B, 96, 32)
    const float* __restrict__ fiw,      // (128, 96)
    const float* __restrict__ fib,      // (128,)
    const float* __restrict__ bnw_g,    // (4, 128)
    const float* __restrict__ ipw,      // (4, 552, 128)
    const float* __restrict__ cw,       // (4, 288, 4)
    const float* __restrict__ cb,       // (4, 288)
    const float* __restrict__ dtb,      // (4, 8)
    const float* __restrict__ alog,     // (4, 8)
    const float* __restrict__ Dp,       // (4, 8)
    const float* __restrict__ mnw,      // (4, 256)
    const float* __restrict__ opw,      // (4, 128, 256)
    const float* __restrict__ nfw,      // (2, 128)
    const float* __restrict__ fow,      // (12, 128)
    const float* __restrict__ fob,      // (12,)
    const float* __restrict__ olw,      // (1, 32)
    const float* __restrict__ olb,      // (1,)
    float* __restrict__ out)            // y (B,12) then buf (B,96,32)
{
    extern __shared__ float sm[];
    float* s_buf  = sm + OFF_BUF;
    float* s_hs   = sm + OFF_HS;
    float* s_zx   = sm + OFF_ZX;
    float* s_bnw  = sm + OFF_BNW;
    float* s_dt   = sm + OFF_DT;
    float* s_dA   = sm + OFF_DA;
    float* s_inv  = sm + OFF_INV;
    float* s_inv2 = sm + OFF_INV2;
    float* s_A    = sm + OFF_ACC;

    const int b    = blockIdx.x;
    const int tid  = threadIdx.x;
    const int lane = tid & 31;
    const int warp = tid >> 5;

    // ---- Stage 0: shifted buffer -> smem + write buf output ------------------
    {
        const float* bsrc = buffer + (size_t)b * CIN * LSEQ;
        const float* xsrc = x + (size_t)b * CIN;
        float* bdst = out + (size_t)gridDim.x * COUT + (size_t)b * CIN * LSEQ;
        for (int idx = tid; idx < CIN * LSEQ; idx += NT) {
            int c = idx >> 5, l = idx & 31;
            float v = (l < LSEQ - 1) ? bsrc[c * LSEQ + l + 1] : xsrc[c];
            s_buf[idx] = v;
            bdst[idx]  = v;
        }
    }
    if (tid < DM) s_A[tid] = 0.f;
    __syncthreads();

    for (int dir = 0; dir < 2; dir++) {
        // ---- fc_in: hs[t][d] = buf[:,t_src] . fiw[d,:] + fib[d] --------------
        {
            int t    = lane;
            int tsrc = dir ? (LSEQ - 1 - t) : t;
            for (int dd = warp * 16; dd < warp * 16 + 16; dd++) {
                float acc = fib[dd];
                const float4* wrow = reinterpret_cast<const float4*>(fiw + dd * CIN);
#pragma unroll
                for (int cc = 0; cc < CIN / 4; cc++) {
                    float4 w4 = wrow[cc];
                    int c = cc * 4;
                    acc = fmaf(w4.x, s_buf[(c + 0) * LSEQ + tsrc], acc);
                    acc = fmaf(w4.y, s_buf[(c + 1) * LSEQ + tsrc], acc);
                    acc = fmaf(w4.z, s_buf[(c + 2) * LSEQ + tsrc], acc);
                    acc = fmaf(w4.w, s_buf[(c + 3) * LSEQ + tsrc], acc);
                }
                s_hs[t * HS_STRIDE + dd] = acc;
            }
        }
        __syncthreads();

        for (int l = 0; l < 2; l++) {
            const int blk = dir * 2 + l;

            // ---- block rmsnorm factor + stage blk_norm_w ---------------------
            if (tid < DM) s_bnw[tid] = bnw_g[blk * DM + tid];
            {
                int t = tid >> 3, part = tid & 7;
                const float4* hp = reinterpret_cast<const float4*>(s_hs + t * HS_STRIDE + part * 16);
                float s = 0.f;
#pragma unroll
                for (int q = 0; q < 4; q++) {
                    float4 v = hp[q];
                    s += v.x * v.x + v.y * v.y + v.z * v.z + v.w * v.w;
                }
                s += __shfl_xor_sync(0xffffffffu, s, 1);
                s += __shfl_xor_sync(0xffffffffu, s, 2);
                s += __shfl_xor_sync(0xffffffffu, s, 4);
                if (part == 0) s_inv[t] = rsqrtf(s * (1.f / DM) + EPS);
            }
            __syncthreads();

            // ---- in_proj: zx[t][e] = inv[t] * sum_k hs[t][k]*bnw[k]*W[e][k] --
            {
                const float* Wbase = ipw + (size_t)blk * EPROJ * DM;
                for (int e = tid; e < EPROJ; e += NT) {
                    const float4* wrow = reinterpret_cast<const float4*>(Wbase + e * DM);
                    float acc[LSEQ];
#pragma unroll
                    for (int t = 0; t < LSEQ; t++) acc[t] = 0.f;
#pragma unroll 2
                    for (int kc = 0; kc < DM / 4; kc++) {
                        float4 w4 = wrow[kc];
                        float4 g4 = reinterpret_cast<const float4*>(s_bnw)[kc];
                        float wx = w4.x * g4.x, wy = w4.y * g4.y;
                        float wz = w4.z * g4.z, ww = w4.w * g4.w;
                        const float* hb = s_hs + kc * 4;
#pragma unroll
                        for (int t = 0; t < LSEQ; t++) {
                            float4 h4 = *reinterpret_cast<const float4*>(hb + t * HS_STRIDE);
                            acc[t] = fmaf(wx, h4.x, acc[t]);
                            acc[t] = fmaf(wy, h4.y, acc[t]);
                            acc[t] = fmaf(wz, h4.z, acc[t]);
                            acc[t] = fmaf(ww, h4.w, acc[t]);
                        }
                    }
                    float* zc = s_zx + e;
#pragma unroll
                    for (int t = 0; t < LSEQ; t++) zc[t * EPROJ] = acc[t] * s_inv[t];
                }
            }
            __syncthreads();

            // ---- dt/dA (256 threads == 32 t * 8 heads) -----------------------
            {
                int t = tid >> 3, h = tid & 7;
                float v  = s_zx[t * EPROJ + DIN + CDIM + h] + dtb[blk * NH + h];
                float sp = (v > 20.f) ? v : log1pf(__expf(v));
                s_dt[t * NH + h] = sp;
                s_dA[t * NH + h] = __expf(-__expf(alog[blk * NH + h]) * sp);
            }
            // ---- causal depthwise conv (k=4) + silu, in place, 288 channels --
            for (int c = tid; c < CDIM; c += NT) {
                float4 w4 = *reinterpret_cast<const float4*>(cw + ((size_t)blk * CDIM + c) * 4);
                float bb  = cb[blk * CDIM + c];
                float x0 = 0.f, x1 = 0.f, x2 = 0.f;
                float* col = s_zx + DIN + c;
#pragma unroll
                for (int t = 0; t < LSEQ; t++) {
                    float xc = col[t * EPROJ];
                    float o  = fmaf(w4.x, x0, fmaf(w4.y, x1, fmaf(w4.z, x2, fmaf(w4.w, xc, bb))));
                    col[t * EPROJ] = o * sigmoidf_(o);
                    x0 = x1; x1 = x2; x2 = xc;
                }
            }
            __syncthreads();

            // ---- SSM scan: thread = (head, p), N=16 state in registers ------
            {
                int h = tid >> 5;
                float st[DST];
#pragma unroll
                for (int n = 0; n < DST; n++) st[n] = 0.f;
                float dskip = Dp[blk * NH + h];
                for (int t = 0; t < LSEQ; t++) {
                    float* row = s_zx + t * EPROJ;
                    float dAv = s_dA[t * NH + h];
                    float dtv = s_dt[t * NH + h];
                    float xv  = row[DIN + tid];
                    float dtx = dtv * xv;
                    float Bb[DST], Cc[DST];
#pragma unroll
                    for (int q = 0; q < 4; q++) {
                        float4 v = reinterpret_cast<const float4*>(row + 2 * DIN)[q];
                        Bb[4*q] = v.x; Bb[4*q+1] = v.y; Bb[4*q+2] = v.z; Bb[4*q+3] = v.w;
                    }
#pragma unroll
                    for (int q = 0; q < 4; q++) {
                        float4 v = reinterpret_cast<const float4*>(row + 2 * DIN + DST)[q];
                        Cc[4*q] = v.x; Cc[4*q+1] = v.y; Cc[4*q+2] = v.z; Cc[4*q+3] = v.w;
                    }
                    float y = 0.f;
#pragma unroll
                    for (int n = 0; n < DST; n++) {
                        st[n] = fmaf(st[n], dAv, dtx * Bb[n]);
                        y = fmaf(st[n], Cc[n], y);
                    }
                    row[DIN + tid] = fmaf(dskip, xv, y);
                }
            }
            __syncthreads();

            // ---- gate: g = y * silu(z), in place over cols [DIN, 2*DIN) -----
            for (int idx = tid; idx < LSEQ * DIN; idx += NT) {
                int t = idx >> 8, e = idx & 255;
                float* row = s_zx + t * EPROJ;
                float z = row[e];
                row[DIN + e] = row[DIN + e] * z * sigmoidf_(z);
            }
            __syncthreads();

            // ---- mixer rmsnorm factor over g ---------------------------------
            {
                int t = tid >> 3, part = tid & 7;
                const float4* gp = reinterpret_cast<const float4*>(s_zx + t * EPROJ + DIN + part * 32);
                float s = 0.f;
#pragma unroll
                for (int q = 0; q < 8; q++) {
                    float4 v = gp[q];
                    s += v.x * v.x + v.y * v.y + v.z * v.z + v.w * v.w;
                }
                s += __shfl_xor_sync(0xffffffffu, s, 1);
                s += __shfl_xor_sync(0xffffffffu, s, 2);
                s += __shfl_xor_sync(0xffffffffu, s, 4);
                if (part == 0) s_inv2[t] = rsqrtf(s * (1.f / DIN) + EPS);
            }
            __syncthreads();

            // ---- prescale g by inv2[t]*mixer_norm_w[e] -----------------------
            for (int idx = tid; idx < LSEQ * DIN; idx += NT) {
                int t = idx >> 8, e = idx & 255;
                s_zx[t * EPROJ + DIN + e] *= s_inv2[t] * mnw[blk * DIN + e];
            }
            __syncthreads();

            // ---- out_proj + residual: hs[t][d] += g[t][:] . opw[d][:] --------
            {
                int d  = tid & 127;
                int tb = (tid >> 7) * 16;
                const float4* wrow = reinterpret_cast<const float4*>(opw + ((size_t)blk * DM + d) * DIN);
                float acc[16];
#pragma unroll
                for (int i = 0; i < 16; i++) acc[i] = 0.f;
#pragma unroll 2
                for (int ec = 0; ec < DIN / 4; ec++) {
                    float4 w4 = wrow[ec];
#pragma unroll
                    for (int i = 0; i < 16; i++) {
                        float4 g4 = *reinterpret_cast<const float4*>(
                            s_zx + (tb + i) * EPROJ + DIN + ec * 4);
                        acc[i] += w4.x * g4.x + w4.y * g4.y + w4.z * g4.z + w4.w * g4.w;
                    }
                }
#pragma unroll
                for (int i = 0; i < 16; i++) s_hs[(tb + i) * HS_STRIDE + d] += acc[i];
            }
            __syncthreads();
        } // layer

        // ---- final rmsnorm(norm_f) + L-weighted accumulate into A[128] ------
        {
            int t = tid >> 3, part = tid & 7;
            const float4* hp = reinterpret_cast<const float4*>(s_hs + t * HS_STRIDE + part * 16);
            float s = 0.f;
#pragma unroll
            for (int q = 0; q < 4; q++) {
                float4 v = hp[q];
                s += v.x * v.x + v.y * v.y + v.z * v.z + v.w * v.w;
            }
            s += __shfl_xor_sync(0xffffffffu, s, 1);
            s += __shfl_xor_sync(0xffffffffu, s, 2);
            s += __shfl_xor_sync(0xffffffffu, s, 4);
            if (part == 0) s_inv[t] = rsqrtf(s * (1.f / DM) + EPS);
        }
        __syncthreads();
        if (tid < DM) {
            float s = 0.f;
#pragma unroll
            for (int t = 0; t < LSEQ; t++) {
                float wl = olw[dir ? (LSEQ - 1 - t) : t];
                s = fmaf(wl * s_inv[t], s_hs[t * HS_STRIDE + tid], s);
            }
            s_A[tid] += s * nfw[dir * DM + tid];
        }
        __syncthreads();
    } // dir

    // ---- y[b][o] = fc_out_w[o] . A + fc_out_b[o]*sum(wl) + out_lin_b --------
    if (tid < COUT) {
        float Swl = 0.f;
#pragma unroll
        for (int t = 0; t < LSEQ; t++) Swl += olw[t];
        float acc = 0.f;
#pragma unroll 4
        for (int d = 0; d < DM; d++) acc = fmaf(fow[tid * DM + d], s_A[d], acc);
        out[(size_t)b * COUT + tid] = acc + fob[tid] * Swl + olb[0];
    }
}

extern "C" void kernel_launch(void* const* d_in, const int* in_sizes, int n_in,
                              void* d_out, int out_size) {
    const float* x      = (const float*)d_in[0];
    const float* buffer = (const float*)d_in[1];
    const float* fiw    = (const float*)d_in[2];
    const float* fib    = (const float*)d_in[3];
    const float* bnw    = (const float*)d_in[4];
    const float* ipw    = (const float*)d_in[5];
    const float* cw     = (const float*)d_in[6];
    const float* cb     = (const float*)d_in[7];
    const float* dtb    = (const float*)d_in[8];
    const float* alog   = (const float*)d_in[9];
    const float* Dp     = (const float*)d_in[10];
    const float* mnw    = (const float*)d_in[11];
    const float* opw    = (const float*)d_in[12];
    const float* nfw    = (const float*)d_in[13];
    const float* fow    = (const float*)d_in[14];
    const float* fob    = (const float*)d_in[15];
    const float* olw    = (const float*)d_in[16];
    const float* olb    = (const float*)d_in[17];
    float* out = (float*)d_out;

    int B = in_sizes[0] / CIN;   // 1024
    size_t smem_bytes = (size_t)SMEM_FLOATS * sizeof(float);  // 103168

    cudaFuncSetAttribute(mamba_actor_kernel,
                         cudaFuncAttributeMaxDynamicSharedMemorySize,
                         (int)smem_bytes);

    mamba_actor_kernel<<<B, NT, smem_bytes>>>(
        x, buffer, fiw, fib, bnw, ipw, cw, cb, dtb, alog,
        Dp, mnw, opw, nfw, fow, fob, olw, olb, out);
}

// round 4
// speedup vs baseline: 1.3271x; 1.3271x over previous
#include <cuda_runtime.h>
#include <math.h>

#define EPS      1e-5f
#define LSEQ     32
#define DM       128
#define CIN      96
#define COUT     12
#define DIN      256
#define DST      16
#define NH       8
#define CDIM     288          // DIN + 2*DST
#define EPROJ    552          // 2*DIN + 2*DST + NH
#define HS_STRIDE 132
#define NT       256

// transposed weight scratch (device globals — no allocation)
#define IPT_N (4 * DM * EPROJ)     // [blk][k][e] = ipw[e][k]*bnw[k]     282624
#define OPT_N (4 * DIN * DM)       // [blk][e][d] = opw[d][e]*mnw[e]     131072
__device__ float g_ipt[IPT_N];
__device__ float g_opt[OPT_N];

// shared memory layout (floats)
#define OFF_BUF   0                         // CIN*LSEQ      = 3072
#define OFF_HS    (OFF_BUF + CIN*LSEQ)      // LSEQ*132      = 4224
#define OFF_ZX    (OFF_HS + LSEQ*HS_STRIDE) // LSEQ*552      = 17664
#define OFF_DT    (OFF_ZX + LSEQ*EPROJ)     // 256
#define OFF_DA    (OFF_DT + LSEQ*NH)        // 256
#define OFF_INV   (OFF_DA + LSEQ*NH)        // 32
#define OFF_INV2  (OFF_INV + LSEQ)          // 32
#define OFF_ACC   (OFF_INV2 + LSEQ)         // 128
#define SMEM_FLOATS (OFF_ACC + DM)

__device__ __forceinline__ float sigmoidf_(float v) {
    return 1.f / (1.f + __expf(-v));
}

// ---- pre-kernel: transpose + fold norms into weights ------------------------
__global__ void prep_weights(const float* __restrict__ ipw,
                             const float* __restrict__ bnw,
                             const float* __restrict__ opw,
                             const float* __restrict__ mnw) {
    int i = blockIdx.x * blockDim.x + threadIdx.x;
    if (i < IPT_N) {
        int blk = i / (DM * EPROJ);
        int r   = i - blk * (DM * EPROJ);
        int k   = r / EPROJ;
        int e   = r - k * EPROJ;
        g_ipt[i] = ipw[((size_t)blk * EPROJ + e) * DM + k] * bnw[blk * DM + k];
    } else if (i < IPT_N + OPT_N) {
        int j   = i - IPT_N;
        int blk = j / (DIN * DM);
        int r   = j - blk * (DIN * DM);
        int e   = r / DM;
        int d   = r - e * DM;
        g_opt[j] = opw[((size_t)blk * DM + d) * DIN + e] * mnw[blk * DIN + e];
    }
}

__global__ void __launch_bounds__(NT, 2) mamba_actor_kernel(
    const float* __restrict__ x,        // (B, 96)
    const float* __restrict__ buffer,   // (B, 96, 32)
    const float* __restrict__ fiw,      // (128, 96)
    const float* __restrict__ fib,      // (128,)
    const float* __restrict__ cw,       // (4, 288, 4)
    const float* __restrict__ cb,       // (4, 288)
    const float* __restrict__ dtb,      // (4, 8)
    const float* __restrict__ alog,     // (4, 8)
    const float* __restrict__ Dp,       // (4, 8)
    const float* __restrict__ nfw,      // (2, 128)
    const float* __restrict__ fow,      // (12, 128)
    const float* __restrict__ fob,      // (12,)
    const float* __restrict__ olw,      // (1, 32)
    const float* __restrict__ olb,      // (1,)
    float* __restrict__ out)            // y (B,12) then buf (B,96,32)
{
    extern __shared__ float sm[];
    float* s_buf  = sm + OFF_BUF;
    float* s_hs   = sm + OFF_HS;
    float* s_zx   = sm + OFF_ZX;
    float* s_dt   = sm + OFF_DT;
    float* s_dA   = sm + OFF_DA;
    float* s_inv  = sm + OFF_INV;
    float* s_inv2 = sm + OFF_INV2;
    float* s_A    = sm + OFF_ACC;

    const int b    = blockIdx.x;
    const int tid  = threadIdx.x;
    const int lane = tid & 31;
    const int warp = tid >> 5;

    // ---- Stage 0: shifted buffer -> smem + write buf output ------------------
    {
        const float* bsrc = buffer + (size_t)b * CIN * LSEQ;
        const float* xsrc = x + (size_t)b * CIN;
        float* bdst = out + (size_t)gridDim.x * COUT + (size_t)b * CIN * LSEQ;
        for (int idx = tid; idx < CIN * LSEQ; idx += NT) {
            int c = idx >> 5, l = idx & 31;
            float v = (l < LSEQ - 1) ? bsrc[c * LSEQ + l + 1] : xsrc[c];
            s_buf[idx] = v;
            bdst[idx]  = v;
        }
    }
    if (tid < DM) s_A[tid] = 0.f;
    __syncthreads();

    for (int dir = 0; dir < 2; dir++) {
        // ---- fc_in: hs[t][d] = buf[:,t_src] . fiw[d,:] + fib[d] --------------
        {
            int t    = lane;
            int tsrc = dir ? (LSEQ - 1 - t) : t;
            for (int dd = warp * 16; dd < warp * 16 + 16; dd++) {
                float acc = fib[dd];
                const float4* wrow = reinterpret_cast<const float4*>(fiw + dd * CIN);
#pragma unroll
                for (int cc = 0; cc < CIN / 4; cc++) {
                    float4 w4 = wrow[cc];
                    int c = cc * 4;
                    acc = fmaf(w4.x, s_buf[(c + 0) * LSEQ + tsrc], acc);
                    acc = fmaf(w4.y, s_buf[(c + 1) * LSEQ + tsrc], acc);
                    acc = fmaf(w4.z, s_buf[(c + 2) * LSEQ + tsrc], acc);
                    acc = fmaf(w4.w, s_buf[(c + 3) * LSEQ + tsrc], acc);
                }
                s_hs[t * HS_STRIDE + dd] = acc;
            }
        }
        __syncthreads();

        for (int l = 0; l < 2; l++) {
            const int blk = dir * 2 + l;

            // ---- block rmsnorm factor -----------------------------------------
            {
                int t = tid >> 3, part = tid & 7;
                const float4* hp = reinterpret_cast<const float4*>(s_hs + t * HS_STRIDE + part * 16);
                float s = 0.f;
#pragma unroll
                for (int q = 0; q < 4; q++) {
                    float4 v = hp[q];
                    s += v.x * v.x + v.y * v.y + v.z * v.z + v.w * v.w;
                }
                s += __shfl_xor_sync(0xffffffffu, s, 1);
                s += __shfl_xor_sync(0xffffffffu, s, 2);
                s += __shfl_xor_sync(0xffffffffu, s, 4);
                if (part == 0) s_inv[t] = rsqrtf(s * (1.f / DM) + EPS);
            }
            __syncthreads();

            // ---- in_proj: 8t x 4e register tiles, transposed weights ----------
            // zx[t][e] = inv[t] * sum_k hs[t][k] * ipt[blk][k][e]
            {
                const float* Wt = g_ipt + (size_t)blk * DM * EPROJ;
                for (int u = tid; u < EPROJ; u += NT) {
                    int ttile = u / 138;
                    int eg    = u - ttile * 138;
                    int e0 = eg * 4, t0 = ttile * 8;
                    float acc[4][8];
#pragma unroll
                    for (int j = 0; j < 4; j++)
#pragma unroll
                        for (int i = 0; i < 8; i++) acc[j][i] = 0.f;
#pragma unroll 2
                    for (int kc = 0; kc < DM / 4; kc++) {
                        float4 w0 = *reinterpret_cast<const float4*>(Wt + (kc * 4 + 0) * EPROJ + e0);
                        float4 w1 = *reinterpret_cast<const float4*>(Wt + (kc * 4 + 1) * EPROJ + e0);
                        float4 w2 = *reinterpret_cast<const float4*>(Wt + (kc * 4 + 2) * EPROJ + e0);
                        float4 w3 = *reinterpret_cast<const float4*>(Wt + (kc * 4 + 3) * EPROJ + e0);
#pragma unroll
                        for (int i = 0; i < 8; i++) {
                            float4 h = *reinterpret_cast<const float4*>(
                                s_hs + (t0 + i) * HS_STRIDE + kc * 4);
                            acc[0][i] = fmaf(h.x, w0.x, fmaf(h.y, w1.x, fmaf(h.z, w2.x, fmaf(h.w, w3.x, acc[0][i]))));
                            acc[1][i] = fmaf(h.x, w0.y, fmaf(h.y, w1.y, fmaf(h.z, w2.y, fmaf(h.w, w3.y, acc[1][i]))));
                            acc[2][i] = fmaf(h.x, w0.z, fmaf(h.y, w1.z, fmaf(h.z, w2.z, fmaf(h.w, w3.z, acc[2][i]))));
                            acc[3][i] = fmaf(h.x, w0.w, fmaf(h.y, w1.w, fmaf(h.z, w2.w, fmaf(h.w, w3.w, acc[3][i]))));
                        }
                    }
#pragma unroll
                    for (int i = 0; i < 8; i++) {
                        float inv = s_inv[t0 + i];
                        float4 o;
                        o.x = acc[0][i] * inv; o.y = acc[1][i] * inv;
                        o.z = acc[2][i] * inv; o.w = acc[3][i] * inv;
                        *reinterpret_cast<float4*>(s_zx + (t0 + i) * EPROJ + e0) = o;
                    }
                }
            }
            __syncthreads();

            // ---- dt/dA (256 threads == 32 t * 8 heads) -----------------------
            {
                int t = tid >> 3, h = tid & 7;
                float v  = s_zx[t * EPROJ + DIN + CDIM + h] + dtb[blk * NH + h];
                float sp = (v > 20.f) ? v : log1pf(__expf(v));
                s_dt[t * NH + h] = sp;
                s_dA[t * NH + h] = __expf(-__expf(alog[blk * NH + h]) * sp);
            }
            // ---- causal depthwise conv (k=4) + silu, in place, 288 channels --
            for (int c = tid; c < CDIM; c += NT) {
                float4 w4 = *reinterpret_cast<const float4*>(cw + ((size_t)blk * CDIM + c) * 4);
                float bb  = cb[blk * CDIM + c];
                float x0 = 0.f, x1 = 0.f, x2 = 0.f;
                float* col = s_zx + DIN + c;
#pragma unroll
                for (int t = 0; t < LSEQ; t++) {
                    float xc = col[t * EPROJ];
                    float o  = fmaf(w4.x, x0, fmaf(w4.y, x1, fmaf(w4.z, x2, fmaf(w4.w, xc, bb))));
                    col[t * EPROJ] = o * sigmoidf_(o);
                    x0 = x1; x1 = x2; x2 = xc;
                }
            }
            __syncthreads();

            // ---- SSM scan: thread = (head, p), N=16 state in registers ------
            {
                int h = tid >> 5;
                float st[DST];
#pragma unroll
                for (int n = 0; n < DST; n++) st[n] = 0.f;
                float dskip = Dp[blk * NH + h];
                for (int t = 0; t < LSEQ; t++) {
                    float* row = s_zx + t * EPROJ;
                    float dAv = s_dA[t * NH + h];
                    float dtv = s_dt[t * NH + h];
                    float xv  = row[DIN + tid];
                    float dtx = dtv * xv;
                    float Bb[DST], Cc[DST];
#pragma unroll
                    for (int q = 0; q < 4; q++) {
                        float4 v = reinterpret_cast<const float4*>(row + 2 * DIN)[q];
                        Bb[4*q] = v.x; Bb[4*q+1] = v.y; Bb[4*q+2] = v.z; Bb[4*q+3] = v.w;
                    }
#pragma unroll
                    for (int q = 0; q < 4; q++) {
                        float4 v = reinterpret_cast<const float4*>(row + 2 * DIN + DST)[q];
                        Cc[4*q] = v.x; Cc[4*q+1] = v.y; Cc[4*q+2] = v.z; Cc[4*q+3] = v.w;
                    }
                    float y = 0.f;
#pragma unroll
                    for (int n = 0; n < DST; n++) {
                        st[n] = fmaf(st[n], dAv, dtx * Bb[n]);
                        y = fmaf(st[n], Cc[n], y);
                    }
                    row[DIN + tid] = fmaf(dskip, xv, y);
                }
            }
            __syncthreads();

            // ---- gate: g = y * silu(z), in place over cols [DIN, 2*DIN) -----
            for (int idx = tid; idx < LSEQ * DIN; idx += NT) {
                int t = idx >> 8, e = idx & 255;
                float* row = s_zx + t * EPROJ;
                float z = row[e];
                row[DIN + e] = row[DIN + e] * z * sigmoidf_(z);
            }
            __syncthreads();

            // ---- mixer rmsnorm factor over g ---------------------------------
            {
                int t = tid >> 3, part = tid & 7;
                const float4* gp = reinterpret_cast<const float4*>(s_zx + t * EPROJ + DIN + part * 32);
                float s = 0.f;
#pragma unroll
                for (int q = 0; q < 8; q++) {
                    float4 v = gp[q];
                    s += v.x * v.x + v.y * v.y + v.z * v.z + v.w * v.w;
                }
                s += __shfl_xor_sync(0xffffffffu, s, 1);
                s += __shfl_xor_sync(0xffffffffu, s, 2);
                s += __shfl_xor_sync(0xffffffffu, s, 4);
                if (part == 0) s_inv2[t] = rsqrtf(s * (1.f / DIN) + EPS);
            }
            __syncthreads();

            // ---- out_proj + residual: 8t x 2d tiles, transposed weights ------
            // hs[t][d] += inv2[t] * sum_e g[t][e] * opt[blk][e][d]
            {
                int ttile = tid >> 6;          // 0..3
                int dg    = tid & 63;          // 0..63
                int t0 = ttile * 8, d0 = dg * 2;
                const float* Ot = g_opt + (size_t)blk * DIN * DM;
                float acc[2][8];
#pragma unroll
                for (int j = 0; j < 2; j++)
#pragma unroll
                    for (int i = 0; i < 8; i++) acc[j][i] = 0.f;
#pragma unroll 2
                for (int ec = 0; ec < DIN / 4; ec++) {
                    float2 w0 = *reinterpret_cast<const float2*>(Ot + (ec * 4 + 0) * DM + d0);
                    float2 w1 = *reinterpret_cast<const float2*>(Ot + (ec * 4 + 1) * DM + d0);
                    float2 w2 = *reinterpret_cast<const float2*>(Ot + (ec * 4 + 2) * DM + d0);
                    float2 w3 = *reinterpret_cast<const float2*>(Ot + (ec * 4 + 3) * DM + d0);
#pragma unroll
                    for (int i = 0; i < 8; i++) {
                        float4 g = *reinterpret_cast<const float4*>(
                            s_zx + (t0 + i) * EPROJ + DIN + ec * 4);
                        acc[0][i] = fmaf(g.x, w0.x, fmaf(g.y, w1.x, fmaf(g.z, w2.x, fmaf(g.w, w3.x, acc[0][i]))));
                        acc[1][i] = fmaf(g.x, w0.y, fmaf(g.y, w1.y, fmaf(g.z, w2.y, fmaf(g.w, w3.y, acc[1][i]))));
                    }
                }
#pragma unroll
                for (int i = 0; i < 8; i++) {
                    int t = t0 + i;
                    float inv2 = s_inv2[t];
                    float* hp = s_hs + t * HS_STRIDE + d0;
                    hp[0] += acc[0][i] * inv2;
                    hp[1] += acc[1][i] * inv2;
                }
            }
            __syncthreads();
        } // layer

        // ---- final rmsnorm(norm_f) + L-weighted accumulate into A[128] ------
        {
            int t = tid >> 3, part = tid & 7;
            const float4* hp = reinterpret_cast<const float4*>(s_hs + t * HS_STRIDE + part * 16);
            float s = 0.f;
#pragma unroll
            for (int q = 0; q < 4; q++) {
                float4 v = hp[q];
                s += v.x * v.x + v.y * v.y + v.z * v.z + v.w * v.w;
            }
            s += __shfl_xor_sync(0xffffffffu, s, 1);
            s += __shfl_xor_sync(0xffffffffu, s, 2);
            s += __shfl_xor_sync(0xffffffffu, s, 4);
            if (part == 0) s_inv[t] = rsqrtf(s * (1.f / DM) + EPS);
        }
        __syncthreads();
        if (tid < DM) {
            float s = 0.f;
#pragma unroll
            for (int t = 0; t < LSEQ; t++) {
                float wl = olw[dir ? (LSEQ - 1 - t) : t];
                s = fmaf(wl * s_inv[t], s_hs[t * HS_STRIDE + tid], s);
            }
            s_A[tid] += s * nfw[dir * DM + tid];
        }
        __syncthreads();
    } // dir

    // ---- y[b][o] = fc_out_w[o] . A + fc_out_b[o]*sum(wl) + out_lin_b --------
    if (tid < COUT) {
        float Swl = 0.f;
#pragma unroll
        for (int t = 0; t < LSEQ; t++) Swl += olw[t];
        float acc = 0.f;
#pragma unroll 4
        for (int d = 0; d < DM; d++) acc = fmaf(fow[tid * DM + d], s_A[d], acc);
        out[(size_t)b * COUT + tid] = acc + fob[tid] * Swl + olb[0];
    }
}

extern "C" void kernel_launch(void* const* d_in, const int* in_sizes, int n_in,
                              void* d_out, int out_size) {
    const float* x      = (const float*)d_in[0];
    const float* buffer = (const float*)d_in[1];
    const float* fiw    = (const float*)d_in[2];
    const float* fib    = (const float*)d_in[3];
    const float* bnw    = (const float*)d_in[4];
    const float* ipw    = (const float*)d_in[5];
    const float* cw     = (const float*)d_in[6];
    const float* cb     = (const float*)d_in[7];
    const float* dtb    = (const float*)d_in[8];
    const float* alog   = (const float*)d_in[9];
    const float* Dp     = (const float*)d_in[10];
    const float* mnw    = (const float*)d_in[11];
    const float* opw    = (const float*)d_in[12];
    const float* nfw    = (const float*)d_in[13];
    const float* fow    = (const float*)d_in[14];
    const float* fob    = (const float*)d_in[15];
    const float* olw    = (const float*)d_in[16];
    const float* olb    = (const float*)d_in[17];
    float* out = (float*)d_out;

    int B = in_sizes[0] / CIN;   // 1024
    size_t smem_bytes = (size_t)SMEM_FLOATS * sizeof(float);

    cudaFuncSetAttribute(mamba_actor_kernel,
                         cudaFuncAttributeMaxDynamicSharedMemorySize,
                         (int)smem_bytes);

    int prep_total = IPT_N + OPT_N;
    prep_weights<<<(prep_total + 255) / 256, 256>>>(ipw, bnw, opw, mnw);

    mamba_actor_kernel<<<B, NT, smem_bytes>>>(
        x, buffer, fiw, fib, cw, cb, dtb, alog,
        Dp, nfw, fow, fob, olw, olb, out);
}

// round 5
// speedup vs baseline: 1.4110x; 1.0633x over previous
#include <cuda_runtime.h>
#include <math.h>

#define EPS      1e-5f
#define LSEQ     32
#define DM       128
#define CIN      96
#define COUT     12
#define DIN      256
#define DST      16
#define NH       8
#define CDIM     288          // DIN + 2*DST
#define EPROJ    552          // 2*DIN + 2*DST + NH
#define HS_STRIDE 132
#define NT       256
#define MAXB     1024

// device scratch (no allocation)
#define IPT_N (4 * DM * EPROJ)     // [blk][k][e] = ipw[e][k]*bnw[k]
#define OPT_N (4 * DIN * DM)       // [blk][e][d] = opw[d][e]*mnw[e]
__device__ float g_ipt[IPT_N];
__device__ float g_opt[OPT_N];
__device__ float g_A[(size_t)MAXB * 2 * DM];   // per (b, dir) accumulator

// shared memory layout (floats)
#define OFF_BUF   0                         // CIN*LSEQ      = 3072
#define OFF_HS    (OFF_BUF + CIN*LSEQ)      // LSEQ*132      = 4224
#define OFF_ZX    (OFF_HS + LSEQ*HS_STRIDE) // LSEQ*552      = 17664
#define OFF_DT    (OFF_ZX + LSEQ*EPROJ)     // 256
#define OFF_DA    (OFF_DT + LSEQ*NH)        // 256
#define OFF_INV   (OFF_DA + LSEQ*NH)        // 32
#define OFF_INV2  (OFF_INV + LSEQ)          // 32
#define SMEM_FLOATS (OFF_INV2 + LSEQ)       // 25536 floats = 102144 B

__device__ __forceinline__ float sigmoidf_(float v) {
    return 1.f / (1.f + __expf(-v));
}

// ---- pre-kernel: transpose + fold norms into weights ------------------------
__global__ void prep_weights(const float* __restrict__ ipw,
                             const float* __restrict__ bnw,
                             const float* __restrict__ opw,
                             const float* __restrict__ mnw) {
    int i = blockIdx.x * blockDim.x + threadIdx.x;
    if (i < IPT_N) {
        int blk = i / (DM * EPROJ);
        int r   = i - blk * (DM * EPROJ);
        int k   = r / EPROJ;
        int e   = r - k * EPROJ;
        g_ipt[i] = ipw[((size_t)blk * EPROJ + e) * DM + k] * bnw[blk * DM + k];
    } else if (i < IPT_N + OPT_N) {
        int j   = i - IPT_N;
        int blk = j / (DIN * DM);
        int r   = j - blk * (DIN * DM);
        int e   = r / DM;
        int d   = r - e * DM;
        g_opt[j] = opw[((size_t)blk * DM + d) * DIN + e] * mnw[blk * DIN + e];
    }
}

// ---- finalize: y[b][o] = fow[o] . (A0+A1) + fob[o]*sum(olw) + olb -----------
__global__ void finalize_kernel(const float* __restrict__ fow,
                                const float* __restrict__ fob,
                                const float* __restrict__ olw,
                                const float* __restrict__ olb,
                                float* __restrict__ out, int B) {
    int idx = blockIdx.x * blockDim.x + threadIdx.x;
    if (idx >= B * COUT) return;
    int b = idx / COUT, o = idx - b * COUT;
    float Swl = 0.f;
#pragma unroll
    for (int t = 0; t < LSEQ; t++) Swl += olw[t];
    const float* A0 = g_A + (size_t)b * 2 * DM;
    float acc = 0.f;
#pragma unroll 4
    for (int d = 0; d < DM; d++) acc = fmaf(fow[o * DM + d], A0[d] + A0[DM + d], acc);
    out[idx] = acc + fob[o] * Swl + olb[0];
}

// ---- main: one CTA per (batch, direction) -----------------------------------
__global__ void __launch_bounds__(NT, 2) mamba_actor_kernel(
    const float* __restrict__ x,        // (B, 96)
    const float* __restrict__ buffer,   // (B, 96, 32)
    const float* __restrict__ fiw,      // (128, 96)
    const float* __restrict__ fib,      // (128,)
    const float* __restrict__ cw,       // (4, 288, 4)
    const float* __restrict__ cb,       // (4, 288)
    const float* __restrict__ dtb,      // (4, 8)
    const float* __restrict__ alog,     // (4, 8)
    const float* __restrict__ Dp,       // (4, 8)
    const float* __restrict__ nfw,      // (2, 128)
    const float* __restrict__ olw,      // (1, 32)
    float* __restrict__ out)            // y (B,12) then buf (B,96,32)
{
    extern __shared__ float sm[];
    float* s_buf  = sm + OFF_BUF;
    float* s_hs   = sm + OFF_HS;
    float* s_zx   = sm + OFF_ZX;
    float* s_dt   = sm + OFF_DT;
    float* s_dA   = sm + OFF_DA;
    float* s_inv  = sm + OFF_INV;
    float* s_inv2 = sm + OFF_INV2;

    const int B    = gridDim.x >> 1;
    const int b    = blockIdx.x >> 1;
    const int dir  = blockIdx.x & 1;
    const int tid  = threadIdx.x;
    const int lane = tid & 31;
    const int warp = tid >> 5;

    // ---- Stage 0: shifted buffer -> smem (+ buf output, dir0 only) ----------
    {
        const float* bsrc = buffer + (size_t)b * CIN * LSEQ;
        const float* xsrc = x + (size_t)b * CIN;
        float* bdst = out + (size_t)B * COUT + (size_t)b * CIN * LSEQ;
        for (int idx = tid; idx < CIN * LSEQ; idx += NT) {
            int c = idx >> 5, l = idx & 31;
            float v = (l < LSEQ - 1) ? bsrc[c * LSEQ + l + 1] : xsrc[c];
            s_buf[idx] = v;
            if (dir == 0) bdst[idx] = v;
        }
    }
    __syncthreads();

    // ---- fc_in: hs[t][d] = buf[:,t_src] . fiw[d,:] + fib[d] ------------------
    {
        int t    = lane;
        int tsrc = dir ? (LSEQ - 1 - t) : t;
        for (int dd = warp * 16; dd < warp * 16 + 16; dd++) {
            float acc = fib[dd];
            const float4* wrow = reinterpret_cast<const float4*>(fiw + dd * CIN);
#pragma unroll
            for (int cc = 0; cc < CIN / 4; cc++) {
                float4 w4 = wrow[cc];
                int c = cc * 4;
                acc = fmaf(w4.x, s_buf[(c + 0) * LSEQ + tsrc], acc);
                acc = fmaf(w4.y, s_buf[(c + 1) * LSEQ + tsrc], acc);
                acc = fmaf(w4.z, s_buf[(c + 2) * LSEQ + tsrc], acc);
                acc = fmaf(w4.w, s_buf[(c + 3) * LSEQ + tsrc], acc);
            }
            s_hs[t * HS_STRIDE + dd] = acc;
        }
    }
    __syncthreads();

    for (int l = 0; l < 2; l++) {
        const int blk = dir * 2 + l;

        // ---- block rmsnorm factor --------------------------------------------
        {
            int t = tid >> 3, part = tid & 7;
            const float4* hp = reinterpret_cast<const float4*>(s_hs + t * HS_STRIDE + part * 16);
            float s = 0.f;
#pragma unroll
            for (int q = 0; q < 4; q++) {
                float4 v = hp[q];
                s += v.x * v.x + v.y * v.y + v.z * v.z + v.w * v.w;
            }
            s += __shfl_xor_sync(0xffffffffu, s, 1);
            s += __shfl_xor_sync(0xffffffffu, s, 2);
            s += __shfl_xor_sync(0xffffffffu, s, 4);
            if (part == 0) s_inv[t] = rsqrtf(s * (1.f / DM) + EPS);
        }
        __syncthreads();

        // ---- in_proj: fused 4e x 16t tiles; weights loaded once per thread ---
        // zx[t][e] = inv[t] * sum_k hs[t][k] * ipt[blk][k][e]
        {
            const float* Wt = g_ipt + (size_t)blk * DM * EPROJ;
            // main: cols 0..511. thread = (g = tid&127, tt-pair = tid>>7)
            {
                int g  = tid & 127;
                int t0 = (tid >> 7) * 16;       // 0 or 16
                int e0 = g * 4;
                float acc[4][16];
#pragma unroll
                for (int j = 0; j < 4; j++)
#pragma unroll
                    for (int i = 0; i < 16; i++) acc[j][i] = 0.f;
#pragma unroll 1
                for (int kc = 0; kc < DM / 4; kc++) {
                    float4 w0 = *reinterpret_cast<const float4*>(Wt + (kc * 4 + 0) * EPROJ + e0);
                    float4 w1 = *reinterpret_cast<const float4*>(Wt + (kc * 4 + 1) * EPROJ + e0);
                    float4 w2 = *reinterpret_cast<const float4*>(Wt + (kc * 4 + 2) * EPROJ + e0);
                    float4 w3 = *reinterpret_cast<const float4*>(Wt + (kc * 4 + 3) * EPROJ + e0);
                    const float* hb = s_hs + t0 * HS_STRIDE + kc * 4;
#pragma unroll
                    for (int i = 0; i < 16; i++) {
                        float4 h = *reinterpret_cast<const float4*>(hb + i * HS_STRIDE);
                        acc[0][i] = fmaf(h.x, w0.x, fmaf(h.y, w1.x, fmaf(h.z, w2.x, fmaf(h.w, w3.x, acc[0][i]))));
                        acc[1][i] = fmaf(h.x, w0.y, fmaf(h.y, w1.y, fmaf(h.z, w2.y, fmaf(h.w, w3.y, acc[1][i]))));
                        acc[2][i] = fmaf(h.x, w0.z, fmaf(h.y, w1.z, fmaf(h.z, w2.z, fmaf(h.w, w3.z, acc[2][i]))));
                        acc[3][i] = fmaf(h.x, w0.w, fmaf(h.y, w1.w, fmaf(h.z, w2.w, fmaf(h.w, w3.w, acc[3][i]))));
                    }
                }
#pragma unroll
                for (int i = 0; i < 16; i++) {
                    float inv = s_inv[t0 + i];
                    float4 o;
                    o.x = acc[0][i] * inv; o.y = acc[1][i] * inv;
                    o.z = acc[2][i] * inv; o.w = acc[3][i] * inv;
                    *reinterpret_cast<float4*>(s_zx + (t0 + i) * EPROJ + e0) = o;
                }
            }
            // tail: cols 512..551 as 1e x 8t micro-units on threads 0..159
            if (tid < 160) {
                int e  = 512 + (tid >> 2);
                int t0 = (tid & 3) * 8;
                float acc[8];
#pragma unroll
                for (int i = 0; i < 8; i++) acc[i] = 0.f;
#pragma unroll 2
                for (int kc = 0; kc < DM / 4; kc++) {
                    float w0 = Wt[(kc * 4 + 0) * EPROJ + e];
                    float w1 = Wt[(kc * 4 + 1) * EPROJ + e];
                    float w2 = Wt[(kc * 4 + 2) * EPROJ + e];
                    float w3 = Wt[(kc * 4 + 3) * EPROJ + e];
#pragma unroll
                    for (int i = 0; i < 8; i++) {
                        float4 h = *reinterpret_cast<const float4*>(
                            s_hs + (t0 + i) * HS_STRIDE + kc * 4);
                        acc[i] = fmaf(h.x, w0, fmaf(h.y, w1, fmaf(h.z, w2, fmaf(h.w, w3, acc[i]))));
                    }
                }
#pragma unroll
                for (int i = 0; i < 8; i++)
                    s_zx[(t0 + i) * EPROJ + e] = acc[i] * s_inv[t0 + i];
            }
        }
        __syncthreads();

        // ---- dt/dA (256 threads == 32 t * 8 heads) ---------------------------
        {
            int t = tid >> 3, h = tid & 7;
            float v  = s_zx[t * EPROJ + DIN + CDIM + h] + dtb[blk * NH + h];
            float sp = (v > 20.f) ? v : log1pf(__expf(v));
            s_dt[t * NH + h] = sp;
            s_dA[t * NH + h] = __expf(-__expf(alog[blk * NH + h]) * sp);
        }
        // ---- causal depthwise conv (k=4) + silu, in place, 288 channels ------
        for (int c = tid; c < CDIM; c += NT) {
            float4 w4 = *reinterpret_cast<const float4*>(cw + ((size_t)blk * CDIM + c) * 4);
            float bb  = cb[blk * CDIM + c];
            float x0 = 0.f, x1 = 0.f, x2 = 0.f;
            float* col = s_zx + DIN + c;
#pragma unroll
            for (int t = 0; t < LSEQ; t++) {
                float xc = col[t * EPROJ];
                float o  = fmaf(w4.x, x0, fmaf(w4.y, x1, fmaf(w4.z, x2, fmaf(w4.w, xc, bb))));
                col[t * EPROJ] = o * sigmoidf_(o);
                x0 = x1; x1 = x2; x2 = xc;
            }
        }
        __syncthreads();

        // ---- SSM scan: thread = (head, p), N=16 state in registers ----------
        {
            int h = tid >> 5;
            float st[DST];
#pragma unroll
            for (int n = 0; n < DST; n++) st[n] = 0.f;
            float dskip = Dp[blk * NH + h];
            for (int t = 0; t < LSEQ; t++) {
                float* row = s_zx + t * EPROJ;
                float dAv = s_dA[t * NH + h];
                float dtv = s_dt[t * NH + h];
                float xv  = row[DIN + tid];
                float dtx = dtv * xv;
                float Bb[DST], Cc[DST];
#pragma unroll
                for (int q = 0; q < 4; q++) {
                    float4 v = reinterpret_cast<const float4*>(row + 2 * DIN)[q];
                    Bb[4*q] = v.x; Bb[4*q+1] = v.y; Bb[4*q+2] = v.z; Bb[4*q+3] = v.w;
                }
#pragma unroll
                for (int q = 0; q < 4; q++) {
                    float4 v = reinterpret_cast<const float4*>(row + 2 * DIN + DST)[q];
                    Cc[4*q] = v.x; Cc[4*q+1] = v.y; Cc[4*q+2] = v.z; Cc[4*q+3] = v.w;
                }
                float y = 0.f;
#pragma unroll
                for (int n = 0; n < DST; n++) {
                    st[n] = fmaf(st[n], dAv, dtx * Bb[n]);
                    y = fmaf(st[n], Cc[n], y);
                }
                row[DIN + tid] = fmaf(dskip, xv, y);
            }
        }
        __syncthreads();

        // ---- gate: g = y * silu(z), in place over cols [DIN, 2*DIN) ----------
        for (int idx = tid; idx < LSEQ * DIN; idx += NT) {
            int t = idx >> 8, e = idx & 255;
            float* row = s_zx + t * EPROJ;
            float z = row[e];
            row[DIN + e] = row[DIN + e] * z * sigmoidf_(z);
        }
        __syncthreads();

        // ---- mixer rmsnorm factor over g -------------------------------------
        {
            int t = tid >> 3, part = tid & 7;
            const float4* gp = reinterpret_cast<const float4*>(s_zx + t * EPROJ + DIN + part * 32);
            float s = 0.f;
#pragma unroll
            for (int q = 0; q < 8; q++) {
                float4 v = gp[q];
                s += v.x * v.x + v.y * v.y + v.z * v.z + v.w * v.w;
            }
            s += __shfl_xor_sync(0xffffffffu, s, 1);
            s += __shfl_xor_sync(0xffffffffu, s, 2);
            s += __shfl_xor_sync(0xffffffffu, s, 4);
            if (part == 0) s_inv2[t] = rsqrtf(s * (1.f / DIN) + EPS);
        }
        __syncthreads();

        // ---- out_proj + residual: 2d x 8t tiles, transposed weights ----------
        // hs[t][d] += inv2[t] * sum_e g[t][e] * opt[blk][e][d]
        {
            int ttile = tid >> 6;          // 0..3
            int dg    = tid & 63;          // 0..63
            int t0 = ttile * 8, d0 = dg * 2;
            const float* Ot = g_opt + (size_t)blk * DIN * DM;
            float acc[2][8];
#pragma unroll
            for (int j = 0; j < 2; j++)
#pragma unroll
                for (int i = 0; i < 8; i++) acc[j][i] = 0.f;
#pragma unroll 2
            for (int ec = 0; ec < DIN / 4; ec++) {
                float2 w0 = *reinterpret_cast<const float2*>(Ot + (ec * 4 + 0) * DM + d0);
                float2 w1 = *reinterpret_cast<const float2*>(Ot + (ec * 4 + 1) * DM + d0);
                float2 w2 = *reinterpret_cast<const float2*>(Ot + (ec * 4 + 2) * DM + d0);
                float2 w3 = *reinterpret_cast<const float2*>(Ot + (ec * 4 + 3) * DM + d0);
#pragma unroll
                for (int i = 0; i < 8; i++) {
                    float4 g = *reinterpret_cast<const float4*>(
                        s_zx + (t0 + i) * EPROJ + DIN + ec * 4);
                    acc[0][i] = fmaf(g.x, w0.x, fmaf(g.y, w1.x, fmaf(g.z, w2.x, fmaf(g.w, w3.x, acc[0][i]))));
                    acc[1][i] = fmaf(g.x, w0.y, fmaf(g.y, w1.y, fmaf(g.z, w2.y, fmaf(g.w, w3.y, acc[1][i]))));
                }
            }
#pragma unroll
            for (int i = 0; i < 8; i++) {
                int t = t0 + i;
                float inv2 = s_inv2[t];
                float* hp = s_hs + t * HS_STRIDE + d0;
                hp[0] += acc[0][i] * inv2;
                hp[1] += acc[1][i] * inv2;
            }
        }
        __syncthreads();
    } // layer

    // ---- final rmsnorm(norm_f) + L-weighted accumulate -> g_A ----------------
    {
        int t = tid >> 3, part = tid & 7;
        const float4* hp = reinterpret_cast<const float4*>(s_hs + t * HS_STRIDE + part * 16);
        float s = 0.f;
#pragma unroll
        for (int q = 0; q < 4; q++) {
            float4 v = hp[q];
            s += v.x * v.x + v.y * v.y + v.z * v.z + v.w * v.w;
        }
        s += __shfl_xor_sync(0xffffffffu, s, 1);
        s += __shfl_xor_sync(0xffffffffu, s, 2);
        s += __shfl_xor_sync(0xffffffffu, s, 4);
        if (part == 0) s_inv[t] = rsqrtf(s * (1.f / DM) + EPS);
    }
    __syncthreads();
    if (tid < DM) {
        float s = 0.f;
#pragma unroll
        for (int t = 0; t < LSEQ; t++) {
            float wl = olw[dir ? (LSEQ - 1 - t) : t];
            s = fmaf(wl * s_inv[t], s_hs[t * HS_STRIDE + tid], s);
        }
        g_A[((size_t)b * 2 + dir) * DM + tid] = s * nfw[dir * DM + tid];
    }
}

extern "C" void kernel_launch(void* const* d_in, const int* in_sizes, int n_in,
                              void* d_out, int out_size) {
    const float* x      = (const float*)d_in[0];
    const float* buffer = (const float*)d_in[1];
    const float* fiw    = (const float*)d_in[2];
    const float* fib    = (const float*)d_in[3];
    const float* bnw    = (const float*)d_in[4];
    const float* ipw    = (const float*)d_in[5];
    const float* cw     = (const float*)d_in[6];
    const float* cb     = (const float*)d_in[7];
    const float* dtb    = (const float*)d_in[8];
    const float* alog   = (const float*)d_in[9];
    const float* Dp     = (const float*)d_in[10];
    const float* mnw    = (const float*)d_in[11];
    const float* opw    = (const float*)d_in[12];
    const float* nfw    = (const float*)d_in[13];
    const float* fow    = (const float*)d_in[14];
    const float* fob    = (const float*)d_in[15];
    const float* olw    = (const float*)d_in[16];
    const float* olb    = (const float*)d_in[17];
    float* out = (float*)d_out;

    int B = in_sizes[0] / CIN;   // 1024
    size_t smem_bytes = (size_t)SMEM_FLOATS * sizeof(float);

    cudaFuncSetAttribute(mamba_actor_kernel,
                         cudaFuncAttributeMaxDynamicSharedMemorySize,
                         (int)smem_bytes);

    int prep_total = IPT_N + OPT_N;
    prep_weights<<<(prep_total + 255) / 256, 256>>>(ipw, bnw, opw, mnw);

    mamba_actor_kernel<<<2 * B, NT, smem_bytes>>>(
        x, buffer, fiw, fib, cw, cb, dtb, alog,
        Dp, nfw, olw, out);

    finalize_kernel<<<(B * COUT + 255) / 256, 256>>>(fow, fob, olw, olb, out, B);
}

// round 6
// speedup vs baseline: 1.6136x; 1.1436x over previous
#include <cuda_runtime.h>
#include <math.h>

#define EPS      1e-5f
#define LSEQ     32
#define DM       128
#define CIN      96
#define COUT     12
#define DIN      256
#define DST      16
#define NH       8
#define CDIM     288          // DIN + 2*DST
#define EPROJ    552          // 2*DIN + 2*DST + NH
#define TST      34           // hs transposed stride (LSEQ+2, even for 8B alignment)
#define NT       256
#define MAXB     1024

typedef unsigned long long u64;

// device scratch (no allocation)
#define IPT_N (4 * DM * EPROJ)     // [blk][k][e] = ipw[e][k]*bnw[k]
#define OPT_N (4 * DIN * DM)       // [blk][e][d] = opw[d][e]*mnw[e]
__device__ float g_ipt[IPT_N];
__device__ float g_opt[OPT_N];
__device__ float g_A[(size_t)MAXB * 2 * DM];   // per (b, dir) accumulator

// shared memory layout (floats)
#define OFF_BUF   0                          // 3072
#define OFF_HST   (OFF_BUF + CIN*LSEQ)       // 128*34 = 4352  (hs transposed [d][t])
#define OFF_ZX    (OFF_HST + DM*TST)         // 32*552 = 17664
#define OFF_DT    (OFF_ZX + LSEQ*EPROJ)      // 256
#define OFF_DA    (OFF_DT + LSEQ*NH)         // 256
#define OFF_INV   (OFF_DA + LSEQ*NH)         // 32
#define OFF_INV2  (OFF_INV + LSEQ)           // 32
#define OFF_RED   (OFF_INV2 + LSEQ)          // 256
#define SMEM_FLOATS (OFF_RED + NT)           // 25920 floats = 103680 B

__device__ __forceinline__ float sigmoidf_(float v) {
    return 1.f / (1.f + __expf(-v));
}
__device__ __forceinline__ u64 pk2(float lo, float hi) {
    u64 r; asm("mov.b64 %0,{%1,%2};" : "=l"(r) : "f"(lo), "f"(hi)); return r;
}
__device__ __forceinline__ u64 dup2(float v) { return pk2(v, v); }
__device__ __forceinline__ void upk2(u64 a, float& lo, float& hi) {
    asm("mov.b64 {%0,%1},%2;" : "=f"(lo), "=f"(hi) : "l"(a));
}
__device__ __forceinline__ u64 fma2_(u64 a, u64 b, u64 c) {
    u64 d; asm("fma.rn.f32x2 %0,%1,%2,%3;" : "=l"(d) : "l"(a), "l"(b), "l"(c)); return d;
}
__device__ __forceinline__ u64 mul2_(u64 a, u64 b) {
    u64 d; asm("mul.rn.f32x2 %0,%1,%2;" : "=l"(d) : "l"(a), "l"(b)); return d;
}
__device__ __forceinline__ u64 add2_(u64 a, u64 b) {
    u64 d; asm("add.rn.f32x2 %0,%1,%2;" : "=l"(d) : "l"(a), "l"(b)); return d;
}

// ---- pre-kernel: transpose + fold norms into weights ------------------------
__global__ void prep_weights(const float* __restrict__ ipw,
                             const float* __restrict__ bnw,
                             const float* __restrict__ opw,
                             const float* __restrict__ mnw) {
    int i = blockIdx.x * blockDim.x + threadIdx.x;
    if (i < IPT_N) {
        int blk = i / (DM * EPROJ);
        int r   = i - blk * (DM * EPROJ);
        int k   = r / EPROJ;
        int e   = r - k * EPROJ;
        g_ipt[i] = ipw[((size_t)blk * EPROJ + e) * DM + k] * bnw[blk * DM + k];
    } else if (i < IPT_N + OPT_N) {
        int j   = i - IPT_N;
        int blk = j / (DIN * DM);
        int r   = j - blk * (DIN * DM);
        int e   = r / DM;
        int d   = r - e * DM;
        g_opt[j] = opw[((size_t)blk * DM + d) * DIN + e] * mnw[blk * DIN + e];
    }
}

// ---- finalize: y[b][o] = fow[o] . (A0+A1) + fob[o]*sum(olw) + olb -----------
__global__ void finalize_kernel(const float* __restrict__ fow,
                                const float* __restrict__ fob,
                                const float* __restrict__ olw,
                                const float* __restrict__ olb,
                                float* __restrict__ out, int B) {
    int idx = blockIdx.x * blockDim.x + threadIdx.x;
    if (idx >= B * COUT) return;
    int b = idx / COUT, o = idx - b * COUT;
    float Swl = 0.f;
#pragma unroll
    for (int t = 0; t < LSEQ; t++) Swl += olw[t];
    const float* A0 = g_A + (size_t)b * 2 * DM;
    float acc = 0.f;
#pragma unroll 4
    for (int d = 0; d < DM; d++) acc = fmaf(fow[o * DM + d], A0[d] + A0[DM + d], acc);
    out[idx] = acc + fob[o] * Swl + olb[0];
}

// ---- main: one CTA per (batch, direction) -----------------------------------
__global__ void __launch_bounds__(NT, 2) mamba_actor_kernel(
    const float* __restrict__ x,        // (B, 96)
    const float* __restrict__ buffer,   // (B, 96, 32)
    const float* __restrict__ fiw,      // (128, 96)
    const float* __restrict__ fib,      // (128,)
    const float* __restrict__ cw,       // (4, 288, 4)
    const float* __restrict__ cb,       // (4, 288)
    const float* __restrict__ dtb,      // (4, 8)
    const float* __restrict__ alog,     // (4, 8)
    const float* __restrict__ Dp,       // (4, 8)
    const float* __restrict__ nfw,      // (2, 128)
    const float* __restrict__ olw,      // (1, 32)
    float* __restrict__ out)            // y (B,12) then buf (B,96,32)
{
    extern __shared__ float sm[];
    float* s_buf  = sm + OFF_BUF;
    float* s_hsT  = sm + OFF_HST;   // [d][t], stride TST
    float* s_zx   = sm + OFF_ZX;    // [t][e], stride EPROJ
    float* s_dt   = sm + OFF_DT;
    float* s_dA   = sm + OFF_DA;
    float* s_inv  = sm + OFF_INV;
    float* s_inv2 = sm + OFF_INV2;
    float* s_red  = sm + OFF_RED;

    const int B    = gridDim.x >> 1;
    const int b    = blockIdx.x >> 1;
    const int dir  = blockIdx.x & 1;
    const int tid  = threadIdx.x;
    const int lane = tid & 31;
    const int warp = tid >> 5;

    // ---- Stage 0: shifted buffer -> smem (+ buf output, dir0 only) ----------
    {
        const float* bsrc = buffer + (size_t)b * CIN * LSEQ;
        const float* xsrc = x + (size_t)b * CIN;
        float* bdst = out + (size_t)B * COUT + (size_t)b * CIN * LSEQ;
        for (int idx = tid; idx < CIN * LSEQ; idx += NT) {
            int c = idx >> 5, l = idx & 31;
            float v = (l < LSEQ - 1) ? bsrc[c * LSEQ + l + 1] : xsrc[c];
            s_buf[idx] = v;
            if (dir == 0) bdst[idx] = v;
        }
    }
    __syncthreads();

    // ---- fc_in: hsT[d][t] = buf[:,t_src] . fiw[d,:] + fib[d] ----------------
    {
        int t    = lane;
        int tsrc = dir ? (LSEQ - 1 - t) : t;
        for (int dd = warp * 16; dd < warp * 16 + 16; dd++) {
            float acc = fib[dd];
            const float4* wrow = reinterpret_cast<const float4*>(fiw + dd * CIN);
#pragma unroll
            for (int cc = 0; cc < CIN / 4; cc++) {
                float4 w4 = wrow[cc];
                int c = cc * 4;
                acc = fmaf(w4.x, s_buf[(c + 0) * LSEQ + tsrc], acc);
                acc = fmaf(w4.y, s_buf[(c + 1) * LSEQ + tsrc], acc);
                acc = fmaf(w4.z, s_buf[(c + 2) * LSEQ + tsrc], acc);
                acc = fmaf(w4.w, s_buf[(c + 3) * LSEQ + tsrc], acc);
            }
            s_hsT[dd * TST + t] = acc;
        }
    }
    __syncthreads();

    for (int l = 0; l < 2; l++) {
        const int blk = dir * 2 + l;

        // ---- block rmsnorm over d (transposed layout): warp per d-chunk -----
        {
            float s = 0.f;
#pragma unroll
            for (int q = 0; q < 16; q++) {
                float v = s_hsT[(warp * 16 + q) * TST + lane];
                s += v * v;
            }
            s_red[warp * 32 + lane] = s;
        }
        __syncthreads();
        if (tid < 32) {
            float s = 0.f;
#pragma unroll
            for (int w = 0; w < 8; w++) s += s_red[w * 32 + tid];
            s_inv[tid] = rsqrtf(s * (1.f / DM) + EPS);
        }
        __syncthreads();

        // ---- in_proj (f32x2 over t-pairs): zx[t][e] = inv[t]*sum_k h[k][t]*W[k][e]
        {
            const float* Wt = g_ipt + (size_t)blk * DM * EPROJ;
            // main: cols 0..511. thread = (g = tid&127 -> 4 e-cols, half = tid>>7 -> 16 t)
            {
                int g  = tid & 127;
                int t0 = (tid >> 7) * 16;
                int e0 = g * 4;
                u64 acc[4][8];
#pragma unroll
                for (int j = 0; j < 4; j++)
#pragma unroll
                    for (int p = 0; p < 8; p++) acc[j][p] = 0ull;
#pragma unroll 1
                for (int kc = 0; kc < DM / 4; kc++) {
                    float4 w0 = *reinterpret_cast<const float4*>(Wt + (kc * 4 + 0) * EPROJ + e0);
                    float4 w1 = *reinterpret_cast<const float4*>(Wt + (kc * 4 + 1) * EPROJ + e0);
                    float4 w2 = *reinterpret_cast<const float4*>(Wt + (kc * 4 + 2) * EPROJ + e0);
                    float4 w3 = *reinterpret_cast<const float4*>(Wt + (kc * 4 + 3) * EPROJ + e0);
#pragma unroll
                    for (int k = 0; k < 4; k++) {
                        float4 wk = (k == 0) ? w0 : (k == 1) ? w1 : (k == 2) ? w2 : w3;
                        u64 wx = dup2(wk.x), wy = dup2(wk.y);
                        u64 wz = dup2(wk.z), ww = dup2(wk.w);
                        const u64* hp = reinterpret_cast<const u64*>(
                            s_hsT + (kc * 4 + k) * TST + t0);
#pragma unroll
                        for (int p = 0; p < 8; p++) {
                            u64 h = hp[p];
                            acc[0][p] = fma2_(h, wx, acc[0][p]);
                            acc[1][p] = fma2_(h, wy, acc[1][p]);
                            acc[2][p] = fma2_(h, wz, acc[2][p]);
                            acc[3][p] = fma2_(h, ww, acc[3][p]);
                        }
                    }
                }
#pragma unroll
                for (int p = 0; p < 8; p++) {
                    u64 inv2p = *reinterpret_cast<const u64*>(s_inv + t0 + 2 * p);
                    float4 o0, o1;
                    u64 a;
                    a = mul2_(acc[0][p], inv2p); upk2(a, o0.x, o1.x);
                    a = mul2_(acc[1][p], inv2p); upk2(a, o0.y, o1.y);
                    a = mul2_(acc[2][p], inv2p); upk2(a, o0.z, o1.z);
                    a = mul2_(acc[3][p], inv2p); upk2(a, o0.w, o1.w);
                    *reinterpret_cast<float4*>(s_zx + (t0 + 2 * p + 0) * EPROJ + e0) = o0;
                    *reinterpret_cast<float4*>(s_zx + (t0 + 2 * p + 1) * EPROJ + e0) = o1;
                }
            }
            // tail: cols 512..551, 1 e x 8 t (4 pairs) per thread, threads 0..159
            if (tid < 160) {
                int e  = 512 + (tid >> 2);
                int t0 = (tid & 3) * 8;
                u64 acc[4];
#pragma unroll
                for (int p = 0; p < 4; p++) acc[p] = 0ull;
#pragma unroll 2
                for (int kc = 0; kc < DM / 4; kc++) {
#pragma unroll
                    for (int k = 0; k < 4; k++) {
                        u64 wd = dup2(Wt[(kc * 4 + k) * EPROJ + e]);
                        const u64* hp = reinterpret_cast<const u64*>(
                            s_hsT + (kc * 4 + k) * TST + t0);
#pragma unroll
                        for (int p = 0; p < 4; p++) acc[p] = fma2_(hp[p], wd, acc[p]);
                    }
                }
#pragma unroll
                for (int p = 0; p < 4; p++) {
                    float lo, hi;
                    u64 inv2p = *reinterpret_cast<const u64*>(s_inv + t0 + 2 * p);
                    upk2(mul2_(acc[p], inv2p), lo, hi);
                    s_zx[(t0 + 2 * p + 0) * EPROJ + e] = lo;
                    s_zx[(t0 + 2 * p + 1) * EPROJ + e] = hi;
                }
            }
        }
        __syncthreads();

        // ---- dt/dA (256 threads == 32 t * 8 heads) ---------------------------
        {
            int t = tid >> 3, h = tid & 7;
            float v  = s_zx[t * EPROJ + DIN + CDIM + h] + dtb[blk * NH + h];
            float sp = (v > 20.f) ? v : log1pf(__expf(v));
            s_dt[t * NH + h] = sp;
            s_dA[t * NH + h] = __expf(-__expf(alog[blk * NH + h]) * sp);
        }
        // ---- causal depthwise conv (k=4) + silu, in place, 288 channels ------
        for (int c = tid; c < CDIM; c += NT) {
            float4 w4 = *reinterpret_cast<const float4*>(cw + ((size_t)blk * CDIM + c) * 4);
            float bb  = cb[blk * CDIM + c];
            float x0 = 0.f, x1 = 0.f, x2 = 0.f;
            float* col = s_zx + DIN + c;
#pragma unroll
            for (int t = 0; t < LSEQ; t++) {
                float xc = col[t * EPROJ];
                float o  = fmaf(w4.x, x0, fmaf(w4.y, x1, fmaf(w4.z, x2, fmaf(w4.w, xc, bb))));
                col[t * EPROJ] = o * sigmoidf_(o);
                x0 = x1; x1 = x2; x2 = xc;
            }
        }
        __syncthreads();

        // ---- SSM scan: thread = (head, p); state packed as 8 f32x2 ----------
        {
            int h = tid >> 5;
            u64 st2[NH];
#pragma unroll
            for (int n = 0; n < 8; n++) st2[n] = 0ull;
            float dskip = Dp[blk * NH + h];
            for (int t = 0; t < LSEQ; t++) {
                float* row = s_zx + t * EPROJ;
                float dAv = s_dA[t * NH + h];
                float dtv = s_dt[t * NH + h];
                float xv  = row[DIN + tid];
                u64 dA2  = dup2(dAv);
                u64 dtx2 = dup2(dtv * xv);
                const ulonglong2* Bp = reinterpret_cast<const ulonglong2*>(row + 2 * DIN);
                const ulonglong2* Cp = reinterpret_cast<const ulonglong2*>(row + 2 * DIN + DST);
                u64 y2 = 0ull;
#pragma unroll
                for (int q = 0; q < 4; q++) {
                    ulonglong2 b2 = Bp[q];
                    ulonglong2 c2 = Cp[q];
                    st2[2*q]   = fma2_(st2[2*q],   dA2, mul2_(dtx2, b2.x));
                    y2         = fma2_(st2[2*q],   c2.x, y2);
                    st2[2*q+1] = fma2_(st2[2*q+1], dA2, mul2_(dtx2, b2.y));
                    y2         = fma2_(st2[2*q+1], c2.y, y2);
                }
                float ylo, yhi;
                upk2(y2, ylo, yhi);
                row[DIN + tid] = fmaf(dskip, xv, ylo + yhi);
            }
        }
        __syncthreads();

        // ---- gate: g = y * silu(z), in place over cols [DIN, 2*DIN) ----------
        for (int idx = tid; idx < LSEQ * DIN; idx += NT) {
            int t = idx >> 8, e = idx & 255;
            float* row = s_zx + t * EPROJ;
            float z = row[e];
            row[DIN + e] = row[DIN + e] * z * sigmoidf_(z);
        }
        __syncthreads();

        // ---- mixer rmsnorm factor over g (zx is t-major: old pattern) -------
        {
            int t = tid >> 3, part = tid & 7;
            const float4* gp = reinterpret_cast<const float4*>(s_zx + t * EPROJ + DIN + part * 32);
            float s = 0.f;
#pragma unroll
            for (int q = 0; q < 8; q++) {
                float4 v = gp[q];
                s += v.x * v.x + v.y * v.y + v.z * v.z + v.w * v.w;
            }
            s += __shfl_xor_sync(0xffffffffu, s, 1);
            s += __shfl_xor_sync(0xffffffffu, s, 2);
            s += __shfl_xor_sync(0xffffffffu, s, 4);
            if (part == 0) s_inv2[t] = rsqrtf(s * (1.f / DIN) + EPS);
        }
        __syncthreads();

        // ---- out_proj + residual (f32x2 over t-pairs) ------------------------
        // hsT[d][t] += inv2[t] * sum_e g[t][e] * opt[blk][e][d]
        {
            int ttile = tid >> 6;          // 0..3 -> t0 = ttile*8
            int dg    = tid & 63;          // 0..63 -> d0 = dg*2
            int t0 = ttile * 8, d0 = dg * 2;
            const float* Ot = g_opt + (size_t)blk * DIN * DM;
            u64 acc[2][4];
#pragma unroll
            for (int j = 0; j < 2; j++)
#pragma unroll
                for (int p = 0; p < 4; p++) acc[j][p] = 0ull;
#pragma unroll 1
            for (int ec = 0; ec < DIN / 4; ec++) {
                float2 w0 = *reinterpret_cast<const float2*>(Ot + (ec * 4 + 0) * DM + d0);
                float2 w1 = *reinterpret_cast<const float2*>(Ot + (ec * 4 + 1) * DM + d0);
                float2 w2 = *reinterpret_cast<const float2*>(Ot + (ec * 4 + 2) * DM + d0);
                float2 w3 = *reinterpret_cast<const float2*>(Ot + (ec * 4 + 3) * DM + d0);
                u64 w0x = dup2(w0.x), w1x = dup2(w1.x), w2x = dup2(w2.x), w3x = dup2(w3.x);
                u64 w0y = dup2(w0.y), w1y = dup2(w1.y), w2y = dup2(w2.y), w3y = dup2(w3.y);
#pragma unroll
                for (int p = 0; p < 4; p++) {
                    float4 ga = *reinterpret_cast<const float4*>(
                        s_zx + (t0 + 2 * p + 0) * EPROJ + DIN + ec * 4);
                    float4 gb = *reinterpret_cast<const float4*>(
                        s_zx + (t0 + 2 * p + 1) * EPROJ + DIN + ec * 4);
                    u64 gx = pk2(ga.x, gb.x), gy = pk2(ga.y, gb.y);
                    u64 gz = pk2(ga.z, gb.z), gw = pk2(ga.w, gb.w);
                    acc[0][p] = fma2_(gx, w0x, acc[0][p]);
                    acc[0][p] = fma2_(gy, w1x, acc[0][p]);
                    acc[0][p] = fma2_(gz, w2x, acc[0][p]);
                    acc[0][p] = fma2_(gw, w3x, acc[0][p]);
                    acc[1][p] = fma2_(gx, w0y, acc[1][p]);
                    acc[1][p] = fma2_(gy, w1y, acc[1][p]);
                    acc[1][p] = fma2_(gz, w2y, acc[1][p]);
                    acc[1][p] = fma2_(gw, w3y, acc[1][p]);
                }
            }
#pragma unroll
            for (int j = 0; j < 2; j++)
#pragma unroll
                for (int p = 0; p < 4; p++) {
                    u64 inv2p = *reinterpret_cast<const u64*>(s_inv2 + t0 + 2 * p);
                    u64* hp = reinterpret_cast<u64*>(s_hsT + (d0 + j) * TST + t0 + 2 * p);
                    *hp = fma2_(acc[j][p], inv2p, *hp);
                }
        }
        __syncthreads();
    } // layer

    // ---- final rmsnorm(norm_f) over d (transposed) ----------------------------
    {
        float s = 0.f;
#pragma unroll
        for (int q = 0; q < 16; q++) {
            float v = s_hsT[(warp * 16 + q) * TST + lane];
            s += v * v;
        }
        s_red[warp * 32 + lane] = s;
    }
    __syncthreads();
    if (tid < 32) {
        float s = 0.f;
#pragma unroll
        for (int w = 0; w < 8; w++) s += s_red[w * 32 + tid];
        s_inv[tid] = rsqrtf(s * (1.f / DM) + EPS);
    }
    __syncthreads();

    // ---- L-weighted accumulate -> g_A ----------------------------------------
    if (tid < DM) {
        const float* hrow = s_hsT + tid * TST;
        float s = 0.f;
#pragma unroll
        for (int t = 0; t < LSEQ; t++) {
            float wl = olw[dir ? (LSEQ - 1 - t) : t];
            s = fmaf(wl * s_inv[t], hrow[t], s);
        }
        g_A[((size_t)b * 2 + dir) * DM + tid] = s * nfw[dir * DM + tid];
    }
}

extern "C" void kernel_launch(void* const* d_in, const int* in_sizes, int n_in,
                              void* d_out, int out_size) {
    const float* x      = (const float*)d_in[0];
    const float* buffer = (const float*)d_in[1];
    const float* fiw    = (const float*)d_in[2];
    const float* fib    = (const float*)d_in[3];
    const float* bnw    = (const float*)d_in[4];
    const float* ipw    = (const float*)d_in[5];
    const float* cw     = (const float*)d_in[6];
    const float* cb     = (const float*)d_in[7];
    const float* dtb    = (const float*)d_in[8];
    const float* alog   = (const float*)d_in[9];
    const float* Dp     = (const float*)d_in[10];
    const float* mnw    = (const float*)d_in[11];
    const float* opw    = (const float*)d_in[12];
    const float* nfw    = (const float*)d_in[13];
    const float* fow    = (const float*)d_in[14];
    const float* fob    = (const float*)d_in[15];
    const float* olw    = (const float*)d_in[16];
    const float* olb    = (const float*)d_in[17];
    float* out = (float*)d_out;

    int B = in_sizes[0] / CIN;   // 1024
    size_t smem_bytes = (size_t)SMEM_FLOATS * sizeof(float);

    cudaFuncSetAttribute(mamba_actor_kernel,
                         cudaFuncAttributeMaxDynamicSharedMemorySize,
                         (int)smem_bytes);

    int prep_total = IPT_N + OPT_N;
    prep_weights<<<(prep_total + 255) / 256, 256>>>(ipw, bnw, opw, mnw);

    mamba_actor_kernel<<<2 * B, NT, smem_bytes>>>(
        x, buffer, fiw, fib, cw, cb, dtb, alog,
        Dp, nfw, olw, out);

    finalize_kernel<<<(B * COUT + 255) / 256, 256>>>(fow, fob, olw, olb, out, B);
}

// round 7
// speedup vs baseline: 1.6286x; 1.0093x over previous
#include <cuda_runtime.h>
#include <math.h>

#define EPS      1e-5f
#define LSEQ     32
#define DM       128
#define CIN      96
#define COUT     12
#define DIN      256
#define DST      16
#define NH       8
#define CDIM     288          // DIN + 2*DST
#define EPROJ    552          // 2*DIN + 2*DST + NH
#define TST      34           // hs transposed stride
#define NT       256
#define MAXB     1024

#define IPROW    1104         // dup'd in_proj row: 2 chunks*512 + tail 80
#define OPROW    256          // dup'd out_proj row (128 d * 2)

typedef unsigned long long u64;

// device scratch (no allocation)
#define IPT2_N (4 * DM * IPROW)    // 565248 floats: dup'd [blk][k][...]
#define OPT2_N (4 * DIN * OPROW)   // 262144 floats: dup'd [blk][e][d-dup]
__device__ float g_ipt2[IPT2_N];
__device__ float g_opt2[OPT2_N];
__device__ float g_A[(size_t)MAXB * 2 * DM];

// shared memory layout (floats)
#define OFF_BUF   0                          // 3072
#define OFF_HST   (OFF_BUF + CIN*LSEQ)       // 128*34 = 4352
#define OFF_ZX    (OFF_HST + DM*TST)         // 32*552 = 17664
#define OFF_DT    (OFF_ZX + LSEQ*EPROJ)      // 256
#define OFF_DA    (OFF_DT + LSEQ*NH)         // 256
#define OFF_INV   (OFF_DA + LSEQ*NH)         // 32
#define OFF_INV2  (OFF_INV + LSEQ)           // 32
#define OFF_RED   (OFF_INV2 + LSEQ)          // 256
#define SMEM_FLOATS (OFF_RED + NT)           // 25920 floats = 103680 B

__device__ __forceinline__ float sigmoidf_(float v) {
    return 1.f / (1.f + __expf(-v));
}
__device__ __forceinline__ u64 pk2(float lo, float hi) {
    u64 r; asm("mov.b64 %0,{%1,%2};" : "=l"(r) : "f"(lo), "f"(hi)); return r;
}
__device__ __forceinline__ u64 dup2(float v) { return pk2(v, v); }
__device__ __forceinline__ void upk2(u64 a, float& lo, float& hi) {
    asm("mov.b64 {%0,%1},%2;" : "=f"(lo), "=f"(hi) : "l"(a));
}
__device__ __forceinline__ u64 fma2_(u64 a, u64 b, u64 c) {
    u64 d; asm("fma.rn.f32x2 %0,%1,%2,%3;" : "=l"(d) : "l"(a), "l"(b), "l"(c)); return d;
}
__device__ __forceinline__ u64 mul2_(u64 a, u64 b) {
    u64 d; asm("mul.rn.f32x2 %0,%1,%2;" : "=l"(d) : "l"(a), "l"(b)); return d;
}

// ---- pre-kernel: transpose + fold norms + duplicate weights ------------------
__global__ void prep_weights(const float* __restrict__ ipw,
                             const float* __restrict__ bnw,
                             const float* __restrict__ opw,
                             const float* __restrict__ mnw) {
    int i = blockIdx.x * blockDim.x + threadIdx.x;
    if (i < IPT2_N) {
        int blk = i / (DM * IPROW);
        int r   = i - blk * (DM * IPROW);
        int k   = r / IPROW;
        int p   = r - k * IPROW;
        int e;
        if (p < 1024) {
            int ch = p >> 9, q = p & 511;
            int g = q >> 2, rem = q & 3;
            e = g * 4 + ch * 2 + (rem >> 1);
        } else {
            e = 512 + ((p - 1024) >> 1);
        }
        g_ipt2[i] = ipw[((size_t)blk * EPROJ + e) * DM + k] * bnw[blk * DM + k];
    } else if (i < IPT2_N + OPT2_N) {
        int j   = i - IPT2_N;
        int blk = j >> 16;
        int r   = j & 65535;
        int e   = r >> 8;
        int d   = (r & 255) >> 1;
        g_opt2[j] = opw[((size_t)blk * DM + d) * DIN + e] * mnw[blk * DIN + e];
    }
}

// ---- finalize ----------------------------------------------------------------
__global__ void finalize_kernel(const float* __restrict__ fow,
                                const float* __restrict__ fob,
                                const float* __restrict__ olw,
                                const float* __restrict__ olb,
                                float* __restrict__ out, int B) {
    int idx = blockIdx.x * blockDim.x + threadIdx.x;
    if (idx >= B * COUT) return;
    int b = idx / COUT, o = idx - b * COUT;
    float Swl = 0.f;
#pragma unroll
    for (int t = 0; t < LSEQ; t++) Swl += olw[t];
    const float* A0 = g_A + (size_t)b * 2 * DM;
    float acc = 0.f;
#pragma unroll 4
    for (int d = 0; d < DM; d++) acc = fmaf(fow[o * DM + d], A0[d] + A0[DM + d], acc);
    out[idx] = acc + fob[o] * Swl + olb[0];
}

// ---- main: one CTA per (batch, direction) -------------------------------------
__global__ void __launch_bounds__(NT, 2) mamba_actor_kernel(
    const float* __restrict__ x,        // (B, 96)
    const float* __restrict__ buffer,   // (B, 96, 32)
    const float* __restrict__ fiw,      // (128, 96)
    const float* __restrict__ fib,      // (128,)
    const float* __restrict__ cw,       // (4, 288, 4)
    const float* __restrict__ cb,       // (4, 288)
    const float* __restrict__ dtb,      // (4, 8)
    const float* __restrict__ alog,     // (4, 8)
    const float* __restrict__ Dp,       // (4, 8)
    const float* __restrict__ nfw,      // (2, 128)
    const float* __restrict__ olw,      // (1, 32)
    float* __restrict__ out)
{
    extern __shared__ float sm[];
    float* s_buf  = sm + OFF_BUF;
    float* s_hsT  = sm + OFF_HST;   // [d][t], stride TST
    float* s_zx   = sm + OFF_ZX;    // [t][e], stride EPROJ
    float* s_dt   = sm + OFF_DT;
    float* s_dA   = sm + OFF_DA;
    float* s_inv  = sm + OFF_INV;
    float* s_inv2 = sm + OFF_INV2;
    float* s_red  = sm + OFF_RED;

    const int B    = gridDim.x >> 1;
    const int b    = blockIdx.x >> 1;
    const int dir  = blockIdx.x & 1;
    const int tid  = threadIdx.x;
    const int lane = tid & 31;
    const int warp = tid >> 5;

    // ---- Stage 0: shifted buffer -> smem (dir-flipped) + buf output ----------
    {
        const float* bsrc = buffer + (size_t)b * CIN * LSEQ;
        const float* xsrc = x + (size_t)b * CIN;
        float* bdst = out + (size_t)B * COUT + (size_t)b * CIN * LSEQ;
        for (int idx = tid; idx < CIN * LSEQ; idx += NT) {
            int c = idx >> 5, l = idx & 31;
            float v = (l < LSEQ - 1) ? bsrc[c * LSEQ + l + 1] : xsrc[c];
            int ls = dir ? (LSEQ - 1 - l) : l;
            s_buf[c * LSEQ + ls] = v;
            if (dir == 0) bdst[idx] = v;
        }
    }
    __syncthreads();

    // ---- fc_in (f32x2 over t-pairs): thread = (d, t-half) --------------------
    {
        int d   = tid >> 1;
        int tph = tid & 1;              // covers t = tph*16 .. +16 (8 pairs)
        u64 acc2[8];
        u64 bias = dup2(fib[d]);
#pragma unroll
        for (int p = 0; p < 8; p++) acc2[p] = bias;
        const float4* wrow = reinterpret_cast<const float4*>(fiw + d * CIN);
#pragma unroll 2
        for (int cc = 0; cc < CIN / 4; cc++) {
            float4 w4 = wrow[cc];
            u64 w0 = dup2(w4.x), w1 = dup2(w4.y), w2 = dup2(w4.z), w3 = dup2(w4.w);
            const u64* b0 = reinterpret_cast<const u64*>(s_buf + (cc * 4 + 0) * LSEQ + tph * 16);
            const u64* b1 = reinterpret_cast<const u64*>(s_buf + (cc * 4 + 1) * LSEQ + tph * 16);
            const u64* b2 = reinterpret_cast<const u64*>(s_buf + (cc * 4 + 2) * LSEQ + tph * 16);
            const u64* b3 = reinterpret_cast<const u64*>(s_buf + (cc * 4 + 3) * LSEQ + tph * 16);
#pragma unroll
            for (int p = 0; p < 8; p++) {
                acc2[p] = fma2_(b0[p], w0, acc2[p]);
                acc2[p] = fma2_(b1[p], w1, acc2[p]);
                acc2[p] = fma2_(b2[p], w2, acc2[p]);
                acc2[p] = fma2_(b3[p], w3, acc2[p]);
            }
        }
        u64* hdst = reinterpret_cast<u64*>(s_hsT + d * TST + tph * 16);
#pragma unroll
        for (int p = 0; p < 8; p++) hdst[p] = acc2[p];
    }
    __syncthreads();

    for (int l = 0; l < 2; l++) {
        const int blk = dir * 2 + l;

        // ---- block rmsnorm over d (transposed layout) ------------------------
        {
            float s = 0.f;
#pragma unroll
            for (int q = 0; q < 16; q++) {
                float v = s_hsT[(warp * 16 + q) * TST + lane];
                s += v * v;
            }
            s_red[warp * 32 + lane] = s;
        }
        __syncthreads();
        if (tid < 32) {
            float s = 0.f;
#pragma unroll
            for (int w = 0; w < 8; w++) s += s_red[w * 32 + tid];
            s_inv[tid] = rsqrtf(s * (1.f / DM) + EPS);
        }
        __syncthreads();

        // ---- in_proj (f32x2, pre-dup'd weights) -------------------------------
        {
            const float* Wt = g_ipt2 + (size_t)blk * DM * IPROW;
            // main: cols 0..511
            {
                int g  = tid & 127;
                int t0 = (tid >> 7) * 16;
                int e0 = g * 4;
                u64 acc[4][8];
#pragma unroll
                for (int j = 0; j < 4; j++)
#pragma unroll
                    for (int p = 0; p < 8; p++) acc[j][p] = 0ull;
#pragma unroll 1
                for (int kc = 0; kc < DM / 4; kc++) {
#pragma unroll
                    for (int k = 0; k < 4; k++) {
                        const float* Wrow = Wt + (kc * 4 + k) * IPROW;
                        ulonglong2 wa = *reinterpret_cast<const ulonglong2*>(Wrow + g * 4);
                        ulonglong2 wb = *reinterpret_cast<const ulonglong2*>(Wrow + 512 + g * 4);
                        const u64* hp = reinterpret_cast<const u64*>(
                            s_hsT + (kc * 4 + k) * TST + t0);
#pragma unroll
                        for (int p = 0; p < 8; p++) {
                            u64 h = hp[p];
                            acc[0][p] = fma2_(h, wa.x, acc[0][p]);
                            acc[1][p] = fma2_(h, wa.y, acc[1][p]);
                            acc[2][p] = fma2_(h, wb.x, acc[2][p]);
                            acc[3][p] = fma2_(h, wb.y, acc[3][p]);
                        }
                    }
                }
#pragma unroll
                for (int p = 0; p < 8; p++) {
                    u64 inv2p = *reinterpret_cast<const u64*>(s_inv + t0 + 2 * p);
                    float4 o0, o1;
                    u64 a;
                    a = mul2_(acc[0][p], inv2p); upk2(a, o0.x, o1.x);
                    a = mul2_(acc[1][p], inv2p); upk2(a, o0.y, o1.y);
                    a = mul2_(acc[2][p], inv2p); upk2(a, o0.z, o1.z);
                    a = mul2_(acc[3][p], inv2p); upk2(a, o0.w, o1.w);
                    *reinterpret_cast<float4*>(s_zx + (t0 + 2 * p + 0) * EPROJ + e0) = o0;
                    *reinterpret_cast<float4*>(s_zx + (t0 + 2 * p + 1) * EPROJ + e0) = o1;
                }
            }
            // tail: cols 512..551 (1e x 8t per thread, threads 0..159)
            if (tid < 160) {
                int e  = 512 + (tid >> 2);
                int t0 = (tid & 3) * 8;
                int eoff = 1024 + (e - 512) * 2;
                u64 acc[4];
#pragma unroll
                for (int p = 0; p < 4; p++) acc[p] = 0ull;
#pragma unroll 2
                for (int kc = 0; kc < DM / 4; kc++) {
#pragma unroll
                    for (int k = 0; k < 4; k++) {
                        u64 wd = *reinterpret_cast<const u64*>(
                            Wt + (kc * 4 + k) * IPROW + eoff);
                        const u64* hp = reinterpret_cast<const u64*>(
                            s_hsT + (kc * 4 + k) * TST + t0);
#pragma unroll
                        for (int p = 0; p < 4; p++) acc[p] = fma2_(hp[p], wd, acc[p]);
                    }
                }
#pragma unroll
                for (int p = 0; p < 4; p++) {
                    float lo, hi;
                    u64 inv2p = *reinterpret_cast<const u64*>(s_inv + t0 + 2 * p);
                    upk2(mul2_(acc[p], inv2p), lo, hi);
                    s_zx[(t0 + 2 * p + 0) * EPROJ + e] = lo;
                    s_zx[(t0 + 2 * p + 1) * EPROJ + e] = hi;
                }
            }
        }
        __syncthreads();

        // ---- dt/dA + conv boundary pre-reads ----------------------------------
        {
            int t = tid >> 3, h = tid & 7;
            float v  = s_zx[t * EPROJ + DIN + CDIM + h] + dtb[blk * NH + h];
            float sp = (v > 20.f) ? v : log1pf(__expf(v));
            s_dt[t * NH + h] = sp;
            s_dA[t * NH + h] = __expf(-__expf(alog[blk * NH + h]) * sp);
        }
        float pre[2][3];
        {
            int nb = 0;
            for (int u = tid; u < 2 * CDIM; u += NT) {
                if (u >= CDIM) {
                    float* col = s_zx + DIN + (u - CDIM);
                    pre[nb][0] = col[13 * EPROJ];
                    pre[nb][1] = col[14 * EPROJ];
                    pre[nb][2] = col[15 * EPROJ];
                    nb++;
                }
            }
        }
        __syncthreads();

        // ---- causal depthwise conv (k=4) + silu, (c, t-half) units ------------
        {
            int nb = 0;
            for (int u = tid; u < 2 * CDIM; u += NT) {
                int half = (u >= CDIM);
                int c = half ? u - CDIM : u;
                float4 w4 = *reinterpret_cast<const float4*>(cw + ((size_t)blk * CDIM + c) * 4);
                float bb  = cb[blk * CDIM + c];
                float x0, x1, x2;
                if (half) { x0 = pre[nb][0]; x1 = pre[nb][1]; x2 = pre[nb][2]; nb++; }
                else      { x0 = 0.f; x1 = 0.f; x2 = 0.f; }
                float* col = s_zx + DIN + c + (half ? 16 * EPROJ : 0);
#pragma unroll
                for (int tt = 0; tt < 16; tt++) {
                    float xc = col[tt * EPROJ];
                    float o  = fmaf(w4.x, x0, fmaf(w4.y, x1, fmaf(w4.z, x2, fmaf(w4.w, xc, bb))));
                    col[tt * EPROJ] = o * sigmoidf_(o);
                    x0 = x1; x1 = x2; x2 = xc;
                }
            }
        }
        __syncthreads();

        // ---- SSM scan (+ fused gate): thread = (head, p) ---------------------
        {
            int h = tid >> 5;
            u64 st2[NH];
#pragma unroll
            for (int n = 0; n < 8; n++) st2[n] = 0ull;
            float dskip = Dp[blk * NH + h];
            for (int t = 0; t < LSEQ; t++) {
                float* row = s_zx + t * EPROJ;
                float dAv = s_dA[t * NH + h];
                float dtv = s_dt[t * NH + h];
                float xv  = row[DIN + tid];
                u64 dA2  = dup2(dAv);
                u64 dtx2 = dup2(dtv * xv);
                const ulonglong2* Bp = reinterpret_cast<const ulonglong2*>(row + 2 * DIN);
                const ulonglong2* Cp = reinterpret_cast<const ulonglong2*>(row + 2 * DIN + DST);
                u64 y2 = 0ull;
#pragma unroll
                for (int q = 0; q < 4; q++) {
                    ulonglong2 b2 = Bp[q];
                    ulonglong2 c2 = Cp[q];
                    st2[2*q]   = fma2_(st2[2*q],   dA2, mul2_(dtx2, b2.x));
                    y2         = fma2_(st2[2*q],   c2.x, y2);
                    st2[2*q+1] = fma2_(st2[2*q+1], dA2, mul2_(dtx2, b2.y));
                    y2         = fma2_(st2[2*q+1], c2.y, y2);
                }
                float ylo, yhi;
                upk2(y2, ylo, yhi);
                float yv = fmaf(dskip, xv, ylo + yhi);
                float z  = row[tid];
                row[DIN + tid] = yv * z * sigmoidf_(z);   // fused gate
            }
        }
        __syncthreads();

        // ---- mixer rmsnorm factor over gated g --------------------------------
        {
            int t = tid >> 3, part = tid & 7;
            const float4* gp = reinterpret_cast<const float4*>(s_zx + t * EPROJ + DIN + part * 32);
            float s = 0.f;
#pragma unroll
            for (int q = 0; q < 8; q++) {
                float4 v = gp[q];
                s += v.x * v.x + v.y * v.y + v.z * v.z + v.w * v.w;
            }
            s += __shfl_xor_sync(0xffffffffu, s, 1);
            s += __shfl_xor_sync(0xffffffffu, s, 2);
            s += __shfl_xor_sync(0xffffffffu, s, 4);
            if (part == 0) s_inv2[t] = rsqrtf(s * (1.f / DIN) + EPS);
        }
        __syncthreads();

        // ---- out_proj + residual (f32x2 over t-pairs, pre-dup'd weights) ------
        {
            int ttile = tid >> 6;
            int dg    = tid & 63;
            int t0 = ttile * 8, d0 = dg * 2;
            const float* Ot = g_opt2 + (size_t)blk * DIN * OPROW;
            u64 acc[2][4];
#pragma unroll
            for (int j = 0; j < 2; j++)
#pragma unroll
                for (int p = 0; p < 4; p++) acc[j][p] = 0ull;
#pragma unroll 1
            for (int ec = 0; ec < DIN / 4; ec++) {
                ulonglong2 w0 = *reinterpret_cast<const ulonglong2*>(Ot + (ec * 4 + 0) * OPROW + dg * 4);
                ulonglong2 w1 = *reinterpret_cast<const ulonglong2*>(Ot + (ec * 4 + 1) * OPROW + dg * 4);
                ulonglong2 w2 = *reinterpret_cast<const ulonglong2*>(Ot + (ec * 4 + 2) * OPROW + dg * 4);
                ulonglong2 w3 = *reinterpret_cast<const ulonglong2*>(Ot + (ec * 4 + 3) * OPROW + dg * 4);
#pragma unroll
                for (int p = 0; p < 4; p++) {
                    float4 ga = *reinterpret_cast<const float4*>(
                        s_zx + (t0 + 2 * p + 0) * EPROJ + DIN + ec * 4);
                    float4 gb = *reinterpret_cast<const float4*>(
                        s_zx + (t0 + 2 * p + 1) * EPROJ + DIN + ec * 4);
                    u64 gx = pk2(ga.x, gb.x), gy = pk2(ga.y, gb.y);
                    u64 gz = pk2(ga.z, gb.z), gw = pk2(ga.w, gb.w);
                    acc[0][p] = fma2_(gx, w0.x, acc[0][p]);
                    acc[0][p] = fma2_(gy, w1.x, acc[0][p]);
                    acc[0][p] = fma2_(gz, w2.x, acc[0][p]);
                    acc[0][p] = fma2_(gw, w3.x, acc[0][p]);
                    acc[1][p] = fma2_(gx, w0.y, acc[1][p]);
                    acc[1][p] = fma2_(gy, w1.y, acc[1][p]);
                    acc[1][p] = fma2_(gz, w2.y, acc[1][p]);
                    acc[1][p] = fma2_(gw, w3.y, acc[1][p]);
                }
            }
#pragma unroll
            for (int j = 0; j < 2; j++)
#pragma unroll
                for (int p = 0; p < 4; p++) {
                    u64 inv2p = *reinterpret_cast<const u64*>(s_inv2 + t0 + 2 * p);
                    u64* hp = reinterpret_cast<u64*>(s_hsT + (d0 + j) * TST + t0 + 2 * p);
                    *hp = fma2_(acc[j][p], inv2p, *hp);
                }
        }
        __syncthreads();
    } // layer

    // ---- final rmsnorm(norm_f) over d -----------------------------------------
    {
        float s = 0.f;
#pragma unroll
        for (int q = 0; q < 16; q++) {
            float v = s_hsT[(warp * 16 + q) * TST + lane];
            s += v * v;
        }
        s_red[warp * 32 + lane] = s;
    }
    __syncthreads();
    if (tid < 32) {
        float s = 0.f;
#pragma unroll
        for (int w = 0; w < 8; w++) s += s_red[w * 32 + tid];
        s_inv[tid] = rsqrtf(s * (1.f / DM) + EPS);
    }
    __syncthreads();

    // ---- L-weighted accumulate -> g_A ------------------------------------------
    if (tid < DM) {
        const float* hrow = s_hsT + tid * TST;
        float s = 0.f;
#pragma unroll
        for (int t = 0; t < LSEQ; t++) {
            float wl = olw[dir ? (LSEQ - 1 - t) : t];
            s = fmaf(wl * s_inv[t], hrow[t], s);
        }
        g_A[((size_t)b * 2 + dir) * DM + tid] = s * nfw[dir * DM + tid];
    }
}

extern "C" void kernel_launch(void* const* d_in, const int* in_sizes, int n_in,
                              void* d_out, int out_size) {
    const float* x      = (const float*)d_in[0];
    const float* buffer = (const float*)d_in[1];
    const float* fiw    = (const float*)d_in[2];
    const float* fib    = (const float*)d_in[3];
    const float* bnw    = (const float*)d_in[4];
    const float* ipw    = (const float*)d_in[5];
    const float* cw     = (const float*)d_in[6];
    const float* cb     = (const float*)d_in[7];
    const float* dtb    = (const float*)d_in[8];
    const float* alog   = (const float*)d_in[9];
    const float* Dp     = (const float*)d_in[10];
    const float* mnw    = (const float*)d_in[11];
    const float* opw    = (const float*)d_in[12];
    const float* nfw    = (const float*)d_in[13];
    const float* fow    = (const float*)d_in[14];
    const float* fob    = (const float*)d_in[15];
    const float* olw    = (const float*)d_in[16];
    const float* olb    = (const float*)d_in[17];
    float* out = (float*)d_out;

    int B = in_sizes[0] / CIN;   // 1024
    size_t smem_bytes = (size_t)SMEM_FLOATS * sizeof(float);

    cudaFuncSetAttribute(mamba_actor_kernel,
                         cudaFuncAttributeMaxDynamicSharedMemorySize,
                         (int)smem_bytes);

    int prep_total = IPT2_N + OPT2_N;
    prep_weights<<<(prep_total + 255) / 256, 256>>>(ipw, bnw, opw, mnw);

    mamba_actor_kernel<<<2 * B, NT, smem_bytes>>>(
        x, buffer, fiw, fib, cw, cb, dtb, alog,
        Dp, nfw, olw, out);

    finalize_kernel<<<(B * COUT + 255) / 256, 256>>>(fow, fob, olw, olb, out, B);
}